// round 9
// baseline (speedup 1.0000x reference)
#include <cuda_runtime.h>
#include <cuda_bf16.h>
#include <cstdint>

#define N_NODES 50000
#define E_EDGES 800000
#define EN_TOT  (E_EDGES + N_NODES)
#define IN_CH   256
#define OUT_CH  64
#define HEADS   4
#define HC      256
#define BCOLS   320
#define NEG_SLOPE 0.2f
#define GBLK    782            // ceil(50000/64)
#define SBLK    196            // ceil(50000/256)

// dynamic smem layout for k_gemm (bytes)
#define SM_AF    0                       // 4096 x uint4 = 64 KB
#define SM_SATS  65536                   // 256 f
#define SM_SATD  (SM_SATS + 1024)        // 256 f
#define SM_SA    (SM_SATD + 1024)        // 256 f  [row64][head4]
#define SM_SD    (SM_SA + 1024)          // 256 f
#define SM_TOTAL (SM_SD + 1024)          // 69632 B

// ---------------- device scratch ---------------------------------------------
__device__ uint4    g_Bf[5 * 4096];         // B frags [nb5][kc8][ks2][nt8][lane32]
__device__ float    g_out[(size_t)N_NODES * BCOLS];
__device__ float    g_alog[N_NODES * 8];    // a_src[4] | a_dst[4]  (atomic-accum)
__device__ float    g_den[N_NODES * HEADS];
__device__ float    g_acc[(size_t)N_NODES * OUT_CH];
__device__ int      g_cnt[N_NODES];
__device__ int      g_bsum[SBLK];
__device__ int2     g_edges[EN_TOT];
__device__ int      g_is64;

// ---------------- helpers ----------------------------------------------------
__device__ __forceinline__ int edge_at(const void* ei, int is64, long long idx) {
    return is64 ? (int)((const long long*)ei)[idx] : ((const int*)ei)[idx];
}
__device__ __forceinline__ float lrelu(float a) {
    return (a > 0.f) ? a : NEG_SLOPE * a;
}
__device__ __forceinline__ void cvt_hl(float x, float y, uint32_t& h, uint32_t& l) {
    __nv_bfloat162 hb = __floats2bfloat162_rn(x, y);
    float2 hf = __bfloat1622float2(hb);
    __nv_bfloat162 lb = __floats2bfloat162_rn(x - hf.x, y - hf.y);
    h = *(uint32_t*)&hb;
    l = *(uint32_t*)&lb;
}
#define MMA_BF16(d, a, b0, b1)                                                \
    asm volatile(                                                             \
        "mma.sync.aligned.m16n8k16.row.col.f32.bf16.bf16.f32 "                \
        "{%0,%1,%2,%3}, {%4,%5,%6,%7}, {%8,%9}, {%0,%1,%2,%3};"               \
        : "+f"(d[0]), "+f"(d[1]), "+f"(d[2]), "+f"(d[3])                      \
        : "r"(a.x), "r"(a.y), "r"(a.z), "r"(a.w), "r"(b0), "r"(b1))

// ---------------- k_detect ----------------------------------------------------
__global__ void k_detect(const unsigned* __restrict__ ei_words) {
    __shared__ unsigned s_or;
    if (threadIdx.x == 0) s_or = 0;
    __syncthreads();
    unsigned v = 0;
    for (int i = threadIdx.x; i < 4096; i += blockDim.x)
        v |= ei_words[2 * i + 1];
    if (v) atomicOr(&s_or, 1u);
    __syncthreads();
    if (threadIdx.x == 0) g_is64 = (s_or == 0) ? 1 : 0;
}

// ---------------- k_init: zero acc/den/cnt/alog --------------------------------
__global__ void k_init() {
    long long idx = blockIdx.x * (long long)blockDim.x + threadIdx.x;
    long long stride = (long long)gridDim.x * blockDim.x;
    long long nacc4 = (long long)N_NODES * OUT_CH / 4;
    float4 z = make_float4(0.f, 0.f, 0.f, 0.f);
    for (long long i = idx; i < nacc4; i += stride) ((float4*)g_acc)[i] = z;
    for (long long i = idx; i < (long long)N_NODES * 2; i += stride)
        ((float4*)g_alog)[i] = z;
    for (long long i = idx; i < (long long)N_NODES * HEADS; i += stride)
        g_den[i] = 0.f;
    for (long long i = idx; i < N_NODES; i += stride) g_cnt[i] = 0;
}

// ---------------- counting sort: hist -> scan -> place -------------------------
__global__ void k_hist(const void* __restrict__ ei) {
    int is64 = g_is64;
    int e = blockIdx.x * blockDim.x + threadIdx.x;
    if (e >= EN_TOT) return;
    int s = (e < E_EDGES) ? edge_at(ei, is64, e) : e - E_EDGES;
    atomicAdd(&g_cnt[s], 1);
}

__global__ void k_scanA() {
    __shared__ int sh[256];
    int t = threadIdx.x;
    int idx = blockIdx.x * 256 + t;
    int v = (idx < N_NODES) ? g_cnt[idx] : 0;
    sh[t] = v;
    __syncthreads();
#pragma unroll
    for (int off = 1; off < 256; off <<= 1) {
        int u = (t >= off) ? sh[t - off] : 0;
        __syncthreads();
        sh[t] += u;
        __syncthreads();
    }
    if (idx < N_NODES) g_cnt[idx] = sh[t] - v;
    if (t == 255) g_bsum[blockIdx.x] = sh[255];
}

__global__ void k_scanB() {
    __shared__ int sh[256];
    int t = threadIdx.x;
    int v = (t < SBLK) ? g_bsum[t] : 0;
    sh[t] = v;
    __syncthreads();
#pragma unroll
    for (int off = 1; off < 256; off <<= 1) {
        int u = (t >= off) ? sh[t - off] : 0;
        __syncthreads();
        sh[t] += u;
        __syncthreads();
    }
    if (t < SBLK) g_bsum[t] = sh[t] - v;
}

__global__ void k_scanC() {
    int idx = blockIdx.x * blockDim.x + threadIdx.x;
    if (idx < N_NODES) g_cnt[idx] += g_bsum[idx >> 8];
}

__global__ void k_place(const void* __restrict__ ei) {
    int is64 = g_is64;
    int e = blockIdx.x * blockDim.x + threadIdx.x;
    if (e >= EN_TOT) return;
    int s, d;
    if (e < E_EDGES) {
        s = edge_at(ei, is64, e);
        d = edge_at(ei, is64, E_EDGES + e);
    } else {
        s = d = e - E_EDGES;
    }
    int pos = atomicAdd(&g_cnt[s], 1);
    g_edges[pos] = make_int2(s, d);
}

// ---------------- k_packB ------------------------------------------------------
__global__ void k_packB(const float* __restrict__ W, const float* __restrict__ Wr) {
    int t = blockIdx.x * blockDim.x + threadIdx.x;
    if (t >= 5 * 4096) return;
    int lane = t & 31;
    int nt = (t >> 5) & 7;
    int ks = (t >> 8) & 1;
    int kc = (t >> 9) & 7;
    int nb = t >> 12;

    int col = nb * 64 + nt * 8 + (lane >> 2);
    int tt = lane & 3;
    int k0 = kc * 32 + ks * 16 + tt * 2;

    float b00, b01, b10, b11;
    if (col < HC) {
        b00 = W[(k0) * HC + col];     b01 = W[(k0 + 1) * HC + col];
        b10 = W[(k0 + 8) * HC + col]; b11 = W[(k0 + 9) * HC + col];
    } else {
        int c = col - HC;
        b00 = Wr[(k0) * OUT_CH + c];     b01 = Wr[(k0 + 1) * OUT_CH + c];
        b10 = Wr[(k0 + 8) * OUT_CH + c]; b11 = Wr[(k0 + 9) * OUT_CH + c];
    }
    uint4 o;
    cvt_hl(b00, b01, o.x, o.z);
    cvt_hl(b10, b11, o.y, o.w);
    g_Bf[nb * 4096 + kc * 512 + ks * 256 + nt * 32 + lane] = o;
}

// ---------------- k_gemm: fused convert + mma.sync + logits -------------------
// BM=64, BN=160. grid (2, 782). 8 warps = 2 mrow x 4 ncol; warp = 32 x 40.
__global__ __launch_bounds__(256) void k_gemm(const float* __restrict__ X,
                                              const float* __restrict__ att_src,
                                              const float* __restrict__ att_dst) {
    extern __shared__ char smem[];
    uint4* AF = (uint4*)(smem + SM_AF);     // [kc8][hl2][ks2][mt4][lane32]
    float* satS = (float*)(smem + SM_SATS);
    float* satD = (float*)(smem + SM_SATD);
    float* sA = (float*)(smem + SM_SA);     // [row64][head4]
    float* sD = (float*)(smem + SM_SD);

    int tid = threadIdx.x;
    int lane = tid & 31;
    int wid = tid >> 5;
    int nb = blockIdx.x;           // 0..1 (160 cols each)
    int mb = blockIdx.y;           // 0..781 (64 rows each)

    // load attention vectors + zero logit accumulators
    satS[tid] = att_src[tid];
    satD[tid] = att_dst[tid];
    sA[tid] = 0.f;
    sD[tid] = 0.f;

    // ---- prologue: load A fp32 once, convert to fragment-ordered smem ----
#pragma unroll
    for (int i = 0; i < 8; i++) {
        int s = tid + 256 * i;                 // 0..2047 frag slots
        int ln = s & 31;
        int mt = (s >> 5) & 3;
        int ks = (s >> 7) & 1;
        int kc = s >> 8;
        int r0 = mt * 16 + (ln >> 2);
        int tt = ln & 3;
        int k0 = kc * 32 + ks * 16 + tt * 2;
        int gr0 = mb * 64 + r0;
        int gr1 = gr0 + 8;
        float2 v0 = (gr0 < N_NODES) ? *(const float2*)(X + (size_t)gr0 * IN_CH + k0)
                                    : make_float2(0.f, 0.f);
        float2 v1 = (gr1 < N_NODES) ? *(const float2*)(X + (size_t)gr1 * IN_CH + k0)
                                    : make_float2(0.f, 0.f);
        float2 v2 = (gr0 < N_NODES) ? *(const float2*)(X + (size_t)gr0 * IN_CH + k0 + 8)
                                    : make_float2(0.f, 0.f);
        float2 v3 = (gr1 < N_NODES) ? *(const float2*)(X + (size_t)gr1 * IN_CH + k0 + 8)
                                    : make_float2(0.f, 0.f);
        uint4 hv, lv;
        cvt_hl(v0.x, v0.y, hv.x, lv.x);
        cvt_hl(v1.x, v1.y, hv.y, lv.y);
        cvt_hl(v2.x, v2.y, hv.z, lv.z);
        cvt_hl(v3.x, v3.y, hv.w, lv.w);
        int base = kc * 512 + ks * 128 + mt * 32 + ln;
        AF[base] = hv;            // hl=0
        AF[base + 256] = lv;      // hl=1
    }
    __syncthreads();

    // ---- mainloop ----
    int mrow = wid >> 2;          // 0..1
    int ncol = wid & 3;           // 0..3
    float acc[2][5][4];
#pragma unroll
    for (int a = 0; a < 2; a++)
#pragma unroll
        for (int b = 0; b < 5; b++)
#pragma unroll
            for (int c = 0; c < 4; c++) acc[a][b][c] = 0.f;

#pragma unroll 1
    for (int kc = 0; kc < 8; kc++) {
        uint4 ah[2][2], al[2][2];
#pragma unroll
        for (int ks = 0; ks < 2; ks++)
#pragma unroll
            for (int mt = 0; mt < 2; mt++) {
                int m = mrow * 2 + mt;
                int base = kc * 512 + ks * 128 + m * 32 + lane;
                ah[ks][mt] = AF[base];
                al[ks][mt] = AF[base + 256];
            }
#pragma unroll
        for (int ks = 0; ks < 2; ks++)
#pragma unroll
            for (int nt = 0; nt < 5; nt++) {
                int g = nb * 20 + ncol * 5 + nt;
                uint4 bv = g_Bf[(g >> 3) * 4096 + kc * 512 + ks * 256 +
                                (g & 7) * 32 + lane];
#pragma unroll
                for (int mt = 0; mt < 2; mt++) {
                    MMA_BF16(acc[mt][nt], ah[ks][mt], bv.x, bv.y);
                    MMA_BF16(acc[mt][nt], ah[ks][mt], bv.z, bv.w);
                    MMA_BF16(acc[mt][nt], al[ks][mt], bv.x, bv.y);
                }
            }
    }

    // ---- epilogue: store g_out + fused logits ----
#pragma unroll
    for (int mt = 0; mt < 2; mt++)
#pragma unroll
        for (int nt = 0; nt < 5; nt++) {
            int lr0 = (mrow * 2 + mt) * 16 + (lane >> 2);
            int row0 = mb * 64 + lr0;
            int g = nb * 20 + ncol * 5 + nt;
            int col = g * 8 + (lane & 3) * 2;
            float* p = g_out + (size_t)row0 * BCOLS + col;
            if (row0 < N_NODES)
                *(float2*)p = make_float2(acc[mt][nt][0], acc[mt][nt][1]);
            if (row0 + 8 < N_NODES)
                *(float2*)(p + 8 * BCOLS) = make_float2(acc[mt][nt][2], acc[mt][nt][3]);

            if (col < HC) {
                int head = col >> 6;
                float s0 = acc[mt][nt][0] * satS[col] + acc[mt][nt][1] * satS[col + 1];
                float d0 = acc[mt][nt][0] * satD[col] + acc[mt][nt][1] * satD[col + 1];
                float s1 = acc[mt][nt][2] * satS[col] + acc[mt][nt][3] * satS[col + 1];
                float d1 = acc[mt][nt][2] * satD[col] + acc[mt][nt][3] * satD[col + 1];
#pragma unroll
                for (int o = 1; o < 4; o <<= 1) {
                    s0 += __shfl_xor_sync(0xffffffffu, s0, o);
                    d0 += __shfl_xor_sync(0xffffffffu, d0, o);
                    s1 += __shfl_xor_sync(0xffffffffu, s1, o);
                    d1 += __shfl_xor_sync(0xffffffffu, d1, o);
                }
                if ((lane & 3) == 0) {
                    atomicAdd(&sA[lr0 * 4 + head], s0);
                    atomicAdd(&sD[lr0 * 4 + head], d0);
                    atomicAdd(&sA[(lr0 + 8) * 4 + head], s1);
                    atomicAdd(&sD[(lr0 + 8) * 4 + head], d1);
                }
            }
        }
    __syncthreads();
    {
        int r = tid >> 2;
        int h = tid & 3;
        int n = mb * 64 + r;
        if (n < N_NODES) {
            atomicAdd(&g_alog[n * 8 + h], sA[tid]);
            atomicAdd(&g_alog[n * 8 + 4 + h], sD[tid]);
        }
    }
}

// ---------------- k_sum --------------------------------------------------------
__global__ void k_sum() {
    int e = blockIdx.x * blockDim.x + threadIdx.x;
    if (e >= EN_TOT) return;
    int2 ed = g_edges[e];
    float4 as = *(const float4*)(g_alog + ed.x * 8);
    float4 ad = *(const float4*)(g_alog + ed.y * 8 + 4);
    float e0 = __expf(lrelu(as.x + ad.x));
    float e1 = __expf(lrelu(as.y + ad.y));
    float e2 = __expf(lrelu(as.z + ad.z));
    float e3 = __expf(lrelu(as.w + ad.w));
    float* dst = g_den + ed.y * 4;
    asm volatile("red.global.add.v4.f32 [%0], {%1,%2,%3,%4};"
                 :: "l"(dst), "f"(e0), "f"(e1), "f"(e2), "f"(e3) : "memory");
}

// ---------------- k_invden -----------------------------------------------------
__global__ void k_invden() {
    int i = blockIdx.x * blockDim.x + threadIdx.x;
    if (i < N_NODES * HEADS) g_den[i] = 1.0f / g_den[i];
}

// ---------------- k_scatter: 16 lanes/edge (src-sorted), red.v4 ----------------
__global__ void k_scatter() {
    int lane = threadIdx.x & 31;
    long long e = ((long long)blockIdx.x * blockDim.x + threadIdx.x) >> 4;
    if (e >= EN_TOT) return;
    int sub = lane & 15;
    int2 ed = g_edges[e];
    int s = ed.x, d = ed.y;

    float wt = 0.f;
    if (sub < 4) {
        float a = lrelu(g_alog[s * 8 + sub] + g_alog[d * 8 + 4 + sub]);
        wt = __expf(a) * g_den[d * 4 + sub];
    }
    int base = lane & 16;
    float w0 = __shfl_sync(0xffffffffu, wt, base + 0);
    float w1 = __shfl_sync(0xffffffffu, wt, base + 1);
    float w2 = __shfl_sync(0xffffffffu, wt, base + 2);
    float w3 = __shfl_sync(0xffffffffu, wt, base + 3);

    int c0 = sub * 4;
    const float* src = g_out + (size_t)s * BCOLS + c0;
    float4 x0 = *(const float4*)(src);
    float4 x1 = *(const float4*)(src + 64);
    float4 x2 = *(const float4*)(src + 128);
    float4 x3 = *(const float4*)(src + 192);
    float4 m;
    m.x = fmaf(w0, x0.x, fmaf(w1, x1.x, fmaf(w2, x2.x, w3 * x3.x)));
    m.y = fmaf(w0, x0.y, fmaf(w1, x1.y, fmaf(w2, x2.y, w3 * x3.y)));
    m.z = fmaf(w0, x0.z, fmaf(w1, x1.z, fmaf(w2, x2.z, w3 * x3.z)));
    m.w = fmaf(w0, x0.w, fmaf(w1, x1.w, fmaf(w2, x2.w, w3 * x3.w)));

    float* dst = g_acc + (size_t)d * OUT_CH + c0;
    asm volatile("red.global.add.v4.f32 [%0], {%1,%2,%3,%4};"
                 :: "l"(dst), "f"(m.x), "f"(m.y), "f"(m.z), "f"(m.w) : "memory");
}

// ---------------- k_final ------------------------------------------------------
__global__ void k_final(const float* __restrict__ bias, float* __restrict__ out) {
    int i = blockIdx.x * blockDim.x + threadIdx.x;
    if (i >= N_NODES * 16) return;
    int n = i >> 4;
    int c = (i & 15) * 4;
    float4 a = *(const float4*)(g_acc + (size_t)n * OUT_CH + c);
    float4 b = *(const float4*)(bias + c);
    float4 r = *(const float4*)(g_out + (size_t)n * BCOLS + 256 + c);
    float4 o;
    o.x = fmaxf(0.f, 0.25f * a.x + b.x + r.x);
    o.y = fmaxf(0.f, 0.25f * a.y + b.y + r.y);
    o.z = fmaxf(0.f, 0.25f * a.z + b.z + r.z);
    o.w = fmaxf(0.f, 0.25f * a.w + b.w + r.w);
    *(float4*)(out + (size_t)n * OUT_CH + c) = o;
}

// ---------------- launch -------------------------------------------------------
extern "C" void kernel_launch(void* const* d_in, const int* in_sizes, int n_in,
                              void* d_out, int out_size) {
    const float* x       = (const float*)d_in[0];
    const void*  ei      = d_in[1];
    const float* W       = (const float*)d_in[2];
    const float* att_src = (const float*)d_in[3];
    const float* att_dst = (const float*)d_in[4];
    const float* bias    = (const float*)d_in[5];
    const float* W_res   = (const float*)d_in[6];
    float* out = (float*)d_out;

    cudaFuncSetAttribute(k_gemm, cudaFuncAttributeMaxDynamicSharedMemorySize,
                         SM_TOTAL);

    k_detect<<<1, 256>>>((const unsigned*)ei);
    k_init<<<1024, 256>>>();
    k_hist<<<(EN_TOT + 255) / 256, 256>>>(ei);
    k_scanA<<<SBLK, 256>>>();
    k_scanB<<<1, 256>>>();
    k_scanC<<<SBLK, 256>>>();
    k_place<<<(EN_TOT + 255) / 256, 256>>>(ei);
    k_packB<<<(5 * 4096 + 255) / 256, 256>>>(W, W_res);
    dim3 ggrid(2, GBLK);
    k_gemm<<<ggrid, 256, SM_TOTAL>>>(x, att_src, att_dst);
    k_sum<<<(EN_TOT + 255) / 256, 256>>>();
    k_invden<<<(N_NODES * HEADS + 255) / 256, 256>>>();
    k_scatter<<<(int)(((long long)EN_TOT * 16 + 255) / 256), 256>>>();
    k_final<<<(N_NODES * 16 + 255) / 256, 256>>>(bias, out);
}

// round 10
// speedup vs baseline: 1.1378x; 1.1378x over previous
#include <cuda_runtime.h>
#include <cuda_bf16.h>
#include <cstdint>

#define N_NODES 50000
#define E_EDGES 800000
#define EN_TOT  (E_EDGES + N_NODES)
#define IN_CH   256
#define OUT_CH  64
#define HEADS   4
#define HC      256
#define BCOLS   320
#define NEG_SLOPE 0.2f
#define MBLK    391            // ceil(50000/128)
#define SBLK    196            // ceil(50000/256)
#define ECHUNK  8              // edges per run-length group

// ---------------- device scratch ---------------------------------------------
__device__ uint4    g_Af[MBLK * 8192];      // A frags [mb][kc8][hl2][ks2][mt8][lane32]
__device__ uint4    g_Bf[5 * 4096];         // B frags [nb5][kc8][ks2][nt8][lane32]
__device__ float    g_out[(size_t)N_NODES * BCOLS];
__device__ float    g_alog[N_NODES * 8];    // a_src[4] | a_dst[4]
__device__ float    g_den[N_NODES * HEADS];
__device__ float4   g_ew[EN_TOT];           // per-edge exp(alpha) per head
__device__ float    g_acc[(size_t)N_NODES * OUT_CH];
__device__ int      g_cnt[N_NODES];
__device__ int      g_bsum[SBLK];
__device__ int2     g_edges[EN_TOT];        // DST-sorted (s,d)
__device__ int      g_is64;

// ---------------- helpers ----------------------------------------------------
__device__ __forceinline__ int edge_at(const void* ei, int is64, long long idx) {
    return is64 ? (int)((const long long*)ei)[idx] : ((const int*)ei)[idx];
}
__device__ __forceinline__ float lrelu(float a) {
    return (a > 0.f) ? a : NEG_SLOPE * a;
}
__device__ __forceinline__ void cvt_hl(float x, float y, uint32_t& h, uint32_t& l) {
    __nv_bfloat162 hb = __floats2bfloat162_rn(x, y);
    float2 hf = __bfloat1622float2(hb);
    __nv_bfloat162 lb = __floats2bfloat162_rn(x - hf.x, y - hf.y);
    h = *(uint32_t*)&hb;
    l = *(uint32_t*)&lb;
}
#define MMA_BF16(d, a, b0, b1)                                                \
    asm volatile(                                                             \
        "mma.sync.aligned.m16n8k16.row.col.f32.bf16.bf16.f32 "                \
        "{%0,%1,%2,%3}, {%4,%5,%6,%7}, {%8,%9}, {%0,%1,%2,%3};"               \
        : "+f"(d[0]), "+f"(d[1]), "+f"(d[2]), "+f"(d[3])                      \
        : "r"(a.x), "r"(a.y), "r"(a.z), "r"(a.w), "r"(b0), "r"(b1))
#define REDV4(p, v)                                                           \
    asm volatile("red.global.add.v4.f32 [%0], {%1,%2,%3,%4};"                 \
                 :: "l"(p), "f"((v).x), "f"((v).y), "f"((v).z), "f"((v).w)    \
                 : "memory")

// ---------------- k_detect ----------------------------------------------------
__global__ void k_detect(const unsigned* __restrict__ ei_words) {
    __shared__ unsigned s_or;
    if (threadIdx.x == 0) s_or = 0;
    __syncthreads();
    unsigned v = 0;
    for (int i = threadIdx.x; i < 4096; i += blockDim.x)
        v |= ei_words[2 * i + 1];
    if (v) atomicOr(&s_or, 1u);
    __syncthreads();
    if (threadIdx.x == 0) g_is64 = (s_or == 0) ? 1 : 0;
}

// ---------------- k_init -------------------------------------------------------
__global__ void k_init() {
    long long idx = blockIdx.x * (long long)blockDim.x + threadIdx.x;
    long long stride = (long long)gridDim.x * blockDim.x;
    long long nacc4 = (long long)N_NODES * OUT_CH / 4;
    float4 z = make_float4(0.f, 0.f, 0.f, 0.f);
    for (long long i = idx; i < nacc4; i += stride) ((float4*)g_acc)[i] = z;
    for (long long i = idx; i < (long long)N_NODES * HEADS; i += stride)
        g_den[i] = 0.f;
    for (long long i = idx; i < N_NODES; i += stride) g_cnt[i] = 0;
}

// ---------------- counting sort by DST -----------------------------------------
__global__ void k_hist(const void* __restrict__ ei) {
    int is64 = g_is64;
    int e = blockIdx.x * blockDim.x + threadIdx.x;
    if (e >= EN_TOT) return;
    int d = (e < E_EDGES) ? edge_at(ei, is64, E_EDGES + e) : e - E_EDGES;
    atomicAdd(&g_cnt[d], 1);
}

__global__ void k_scanA() {
    __shared__ int sh[256];
    int t = threadIdx.x;
    int idx = blockIdx.x * 256 + t;
    int v = (idx < N_NODES) ? g_cnt[idx] : 0;
    sh[t] = v;
    __syncthreads();
#pragma unroll
    for (int off = 1; off < 256; off <<= 1) {
        int u = (t >= off) ? sh[t - off] : 0;
        __syncthreads();
        sh[t] += u;
        __syncthreads();
    }
    if (idx < N_NODES) g_cnt[idx] = sh[t] - v;
    if (t == 255) g_bsum[blockIdx.x] = sh[255];
}

__global__ void k_scanB() {
    __shared__ int sh[256];
    int t = threadIdx.x;
    int v = (t < SBLK) ? g_bsum[t] : 0;
    sh[t] = v;
    __syncthreads();
#pragma unroll
    for (int off = 1; off < 256; off <<= 1) {
        int u = (t >= off) ? sh[t - off] : 0;
        __syncthreads();
        sh[t] += u;
        __syncthreads();
    }
    if (t < SBLK) g_bsum[t] = sh[t] - v;
}

__global__ void k_scanC() {
    int idx = blockIdx.x * blockDim.x + threadIdx.x;
    if (idx < N_NODES) g_cnt[idx] += g_bsum[idx >> 8];
}

__global__ void k_place(const void* __restrict__ ei) {
    int is64 = g_is64;
    int e = blockIdx.x * blockDim.x + threadIdx.x;
    if (e >= EN_TOT) return;
    int s, d;
    if (e < E_EDGES) {
        s = edge_at(ei, is64, e);
        d = edge_at(ei, is64, E_EDGES + e);
    } else {
        s = d = e - E_EDGES;
    }
    int pos = atomicAdd(&g_cnt[d], 1);
    g_edges[pos] = make_int2(s, d);
}

// ---------------- k_prep: X -> bf16 hi/lo fragments ----------------------------
__global__ void k_prep(const float* __restrict__ X) {
    int t = blockIdx.x * blockDim.x + threadIdx.x;
    if (t >= MBLK * 4096) return;
    int lane = t & 31;
    int mt = (t >> 5) & 7;
    int ks = (t >> 8) & 1;
    int kc = (t >> 9) & 7;
    int mb = t >> 12;

    int r0 = mb * 128 + mt * 16 + (lane >> 2);
    int tt = lane & 3;
    int k0 = kc * 32 + (ks * 8 + tt) * 2;

    float2 v[4];
    v[0] = (r0 < N_NODES) ? *(const float2*)(X + (size_t)r0 * IN_CH + k0)
                          : make_float2(0.f, 0.f);
    v[1] = (r0 + 8 < N_NODES) ? *(const float2*)(X + (size_t)(r0 + 8) * IN_CH + k0)
                              : make_float2(0.f, 0.f);
    v[2] = (r0 < N_NODES) ? *(const float2*)(X + (size_t)r0 * IN_CH + k0 + 8)
                          : make_float2(0.f, 0.f);
    v[3] = (r0 + 8 < N_NODES) ? *(const float2*)(X + (size_t)(r0 + 8) * IN_CH + k0 + 8)
                              : make_float2(0.f, 0.f);
    uint4 hv, lv;
    cvt_hl(v[0].x, v[0].y, hv.x, lv.x);
    cvt_hl(v[1].x, v[1].y, hv.y, lv.y);
    cvt_hl(v[2].x, v[2].y, hv.z, lv.z);
    cvt_hl(v[3].x, v[3].y, hv.w, lv.w);

    int base = mb * 8192 + kc * 1024 + ks * 256 + mt * 32 + lane;
    g_Af[base] = hv;
    g_Af[base + 512] = lv;
}

// ---------------- k_packB ------------------------------------------------------
__global__ void k_packB(const float* __restrict__ W, const float* __restrict__ Wr) {
    int t = blockIdx.x * blockDim.x + threadIdx.x;
    if (t >= 5 * 4096) return;
    int lane = t & 31;
    int nt = (t >> 5) & 7;
    int ks = (t >> 8) & 1;
    int kc = (t >> 9) & 7;
    int nb = t >> 12;

    int col = nb * 64 + nt * 8 + (lane >> 2);
    int tt = lane & 3;
    int k0 = kc * 32 + ks * 16 + tt * 2;

    float b00, b01, b10, b11;
    if (col < HC) {
        b00 = W[(k0) * HC + col];     b01 = W[(k0 + 1) * HC + col];
        b10 = W[(k0 + 8) * HC + col]; b11 = W[(k0 + 9) * HC + col];
    } else {
        int c = col - HC;
        b00 = Wr[(k0) * OUT_CH + c];     b01 = Wr[(k0 + 1) * OUT_CH + c];
        b10 = Wr[(k0 + 8) * OUT_CH + c]; b11 = Wr[(k0 + 9) * OUT_CH + c];
    }
    uint4 o;
    cvt_hl(b00, b01, o.x, o.z);
    cvt_hl(b10, b11, o.y, o.w);
    g_Bf[nb * 4096 + kc * 512 + ks * 256 + nt * 32 + lane] = o;
}

// ---------------- k_gemm: mma.sync + fused logits (round-8 proven) -------------
__global__ __launch_bounds__(256) void k_gemm(const float* __restrict__ att_src,
                                              const float* __restrict__ att_dst) {
    __shared__ float sAttS[64], sAttD[64], sA[128], sD[128];
    int tid = threadIdx.x;
    int lane = tid & 31;
    int wid = tid >> 5;
    int mrow = wid >> 1;
    int ncol = wid & 1;
    int mb = blockIdx.y;
    int nb = blockIdx.x;

    if (nb < 4) {
        if (tid < 64) {
            sAttS[tid] = att_src[nb * 64 + tid];
            sAttD[tid] = att_dst[nb * 64 + tid];
        }
        if (tid >= 64 && tid < 192) {
            sA[tid - 64] = 0.f;
            sD[tid - 64] = 0.f;
        }
        __syncthreads();
    }

    float acc[2][4][4];
#pragma unroll
    for (int i = 0; i < 2; i++)
#pragma unroll
        for (int j = 0; j < 4; j++)
#pragma unroll
            for (int q = 0; q < 4; q++) acc[i][j][q] = 0.f;

    const uint4* Ab = g_Af + mb * 8192;
    const uint4* Bb = g_Bf + nb * 4096;

#pragma unroll 1
    for (int kc = 0; kc < 8; kc++) {
        const uint4* Ak = Ab + kc * 1024;
        const uint4* Bk = Bb + kc * 512;
        uint4 ah[2][2], al[2][2];
#pragma unroll
        for (int ks = 0; ks < 2; ks++)
#pragma unroll
            for (int mt = 0; mt < 2; mt++) {
                int m = mrow * 2 + mt;
                ah[ks][mt] = Ak[ks * 256 + m * 32 + lane];
                al[ks][mt] = Ak[512 + ks * 256 + m * 32 + lane];
            }
#pragma unroll
        for (int ks = 0; ks < 2; ks++)
#pragma unroll
            for (int j = 0; j < 4; j++) {
                uint4 bv = Bk[ks * 256 + (ncol * 4 + j) * 32 + lane];
#pragma unroll
                for (int mt = 0; mt < 2; mt++) {
                    MMA_BF16(acc[mt][j], ah[ks][mt], bv.x, bv.y);
                    MMA_BF16(acc[mt][j], ah[ks][mt], bv.z, bv.w);
                    MMA_BF16(acc[mt][j], al[ks][mt], bv.x, bv.y);
                }
            }
    }

#pragma unroll
    for (int mt = 0; mt < 2; mt++)
#pragma unroll
        for (int nt = 0; nt < 4; nt++) {
            int row0 = mb * 128 + (mrow * 2 + mt) * 16 + (lane >> 2);
            int col = nb * 64 + (ncol * 4 + nt) * 8 + (lane & 3) * 2;
            float* p = g_out + (size_t)row0 * BCOLS + col;
            if (row0 < N_NODES)
                *(float2*)p = make_float2(acc[mt][nt][0], acc[mt][nt][1]);
            if (row0 + 8 < N_NODES)
                *(float2*)(p + 8 * BCOLS) = make_float2(acc[mt][nt][2], acc[mt][nt][3]);
        }

    if (nb < 4) {
#pragma unroll
        for (int mt = 0; mt < 2; mt++) {
            float s0 = 0.f, d0 = 0.f, s1 = 0.f, d1 = 0.f;
#pragma unroll
            for (int nt = 0; nt < 4; nt++) {
                int cl = (ncol * 4 + nt) * 8 + (lane & 3) * 2;
                float a0 = sAttS[cl], a1 = sAttS[cl + 1];
                float b0 = sAttD[cl], b1 = sAttD[cl + 1];
                s0 += acc[mt][nt][0] * a0 + acc[mt][nt][1] * a1;
                s1 += acc[mt][nt][2] * a0 + acc[mt][nt][3] * a1;
                d0 += acc[mt][nt][0] * b0 + acc[mt][nt][1] * b1;
                d1 += acc[mt][nt][2] * b0 + acc[mt][nt][3] * b1;
            }
#pragma unroll
            for (int o = 1; o < 4; o <<= 1) {
                s0 += __shfl_xor_sync(0xffffffffu, s0, o);
                s1 += __shfl_xor_sync(0xffffffffu, s1, o);
                d0 += __shfl_xor_sync(0xffffffffu, d0, o);
                d1 += __shfl_xor_sync(0xffffffffu, d1, o);
            }
            if ((lane & 3) == 0) {
                int r = (mrow * 2 + mt) * 16 + (lane >> 2);
                atomicAdd(&sA[r], s0);
                atomicAdd(&sD[r], d0);
                atomicAdd(&sA[r + 8], s1);
                atomicAdd(&sD[r + 8], d1);
            }
        }
        __syncthreads();
        for (int r = tid; r < 128; r += 256) {
            int n = mb * 128 + r;
            if (n < N_NODES) {
                g_alog[n * 8 + nb] = sA[r];
                g_alog[n * 8 + 4 + nb] = sD[r];
            }
        }
    }
}

// ---------------- k_sum: 1 thread = ECHUNK dst-sorted edges --------------------
// computes exp vector, stores g_ew, run-length merges den contributions.
__global__ void k_sum() {
    long long g = blockIdx.x * (long long)blockDim.x + threadIdx.x;
    long long e0 = g * ECHUNK;
    if (e0 >= EN_TOT) return;
    float4 acc = make_float4(0.f, 0.f, 0.f, 0.f);
    int dprev = -1;
#pragma unroll
    for (int i = 0; i < ECHUNK; i++) {
        long long e = e0 + i;
        if (e >= EN_TOT) break;
        int2 ed = g_edges[e];
        float4 as = *(const float4*)(g_alog + ed.x * 8);
        float4 ad = *(const float4*)(g_alog + ed.y * 8 + 4);
        float4 ex;
        ex.x = __expf(lrelu(as.x + ad.x));
        ex.y = __expf(lrelu(as.y + ad.y));
        ex.z = __expf(lrelu(as.z + ad.z));
        ex.w = __expf(lrelu(as.w + ad.w));
        g_ew[e] = ex;
        if (ed.y != dprev) {
            if (dprev >= 0) REDV4(g_den + dprev * 4, acc);
            acc = ex;
            dprev = ed.y;
        } else {
            acc.x += ex.x; acc.y += ex.y; acc.z += ex.z; acc.w += ex.w;
        }
    }
    if (dprev >= 0) REDV4(g_den + dprev * 4, acc);
}

// ---------------- k_invden -----------------------------------------------------
__global__ void k_invden() {
    int i = blockIdx.x * blockDim.x + threadIdx.x;
    if (i < N_NODES * HEADS) g_den[i] = 1.0f / g_den[i];
}

// ---------------- k_scatter: 16 lanes x ECHUNK dst-sorted edges ----------------
__global__ void k_scatter() {
    int lane = threadIdx.x & 31;
    int sub = lane & 15;
    long long grp = ((long long)blockIdx.x * blockDim.x + threadIdx.x) >> 4;
    long long e0 = grp * ECHUNK;
    if (e0 >= EN_TOT) return;
    int c0 = sub * 4;

    float4 acc = make_float4(0.f, 0.f, 0.f, 0.f);
    int dprev = -1;
#pragma unroll
    for (int i = 0; i < ECHUNK; i++) {
        long long e = e0 + i;
        if (e >= EN_TOT) break;
        int2 ed = g_edges[e];                       // broadcast load
        float4 w = g_ew[e];                         // broadcast load
        float4 dn = *(const float4*)(g_den + ed.y * 4);
        float w0 = w.x * dn.x, w1 = w.y * dn.y, w2 = w.z * dn.z, w3 = w.w * dn.w;

        const float* src = g_out + (size_t)ed.x * BCOLS + c0;
        float4 x0 = *(const float4*)(src);
        float4 x1 = *(const float4*)(src + 64);
        float4 x2 = *(const float4*)(src + 128);
        float4 x3 = *(const float4*)(src + 192);

        if (ed.y != dprev) {
            if (dprev >= 0)
                REDV4(g_acc + (size_t)dprev * OUT_CH + c0, acc);
            acc = make_float4(0.f, 0.f, 0.f, 0.f);
            dprev = ed.y;
        }
        acc.x += fmaf(w0, x0.x, fmaf(w1, x1.x, fmaf(w2, x2.x, w3 * x3.x)));
        acc.y += fmaf(w0, x0.y, fmaf(w1, x1.y, fmaf(w2, x2.y, w3 * x3.y)));
        acc.z += fmaf(w0, x0.z, fmaf(w1, x1.z, fmaf(w2, x2.z, w3 * x3.z)));
        acc.w += fmaf(w0, x0.w, fmaf(w1, x1.w, fmaf(w2, x2.w, w3 * x3.w)));
    }
    if (dprev >= 0)
        REDV4(g_acc + (size_t)dprev * OUT_CH + c0, acc);
}

// ---------------- k_final ------------------------------------------------------
__global__ void k_final(const float* __restrict__ bias, float* __restrict__ out) {
    int i = blockIdx.x * blockDim.x + threadIdx.x;
    if (i >= N_NODES * 16) return;
    int n = i >> 4;
    int c = (i & 15) * 4;
    float4 a = *(const float4*)(g_acc + (size_t)n * OUT_CH + c);
    float4 b = *(const float4*)(bias + c);
    float4 r = *(const float4*)(g_out + (size_t)n * BCOLS + 256 + c);
    float4 o;
    o.x = fmaxf(0.f, 0.25f * a.x + b.x + r.x);
    o.y = fmaxf(0.f, 0.25f * a.y + b.y + r.y);
    o.z = fmaxf(0.f, 0.25f * a.z + b.z + r.z);
    o.w = fmaxf(0.f, 0.25f * a.w + b.w + r.w);
    *(float4*)(out + (size_t)n * OUT_CH + c) = o;
}

// ---------------- launch -------------------------------------------------------
extern "C" void kernel_launch(void* const* d_in, const int* in_sizes, int n_in,
                              void* d_out, int out_size) {
    const float* x       = (const float*)d_in[0];
    const void*  ei      = d_in[1];
    const float* W       = (const float*)d_in[2];
    const float* att_src = (const float*)d_in[3];
    const float* att_dst = (const float*)d_in[4];
    const float* bias    = (const float*)d_in[5];
    const float* W_res   = (const float*)d_in[6];
    float* out = (float*)d_out;

    k_detect<<<1, 256>>>((const unsigned*)ei);
    k_init<<<1024, 256>>>();
    k_hist<<<(EN_TOT + 255) / 256, 256>>>(ei);
    k_scanA<<<SBLK, 256>>>();
    k_scanB<<<1, 256>>>();
    k_scanC<<<SBLK, 256>>>();
    k_place<<<(EN_TOT + 255) / 256, 256>>>(ei);
    k_prep<<<(MBLK * 4096 + 255) / 256, 256>>>(x);
    k_packB<<<(5 * 4096 + 255) / 256, 256>>>(W, W_res);
    dim3 ggrid(5, MBLK);
    k_gemm<<<ggrid, 256>>>(att_src, att_dst);
    {
        long long ng = (EN_TOT + ECHUNK - 1) / ECHUNK;
        k_sum<<<(int)((ng + 255) / 256), 256>>>();
        k_invden<<<(N_NODES * HEADS + 255) / 256, 256>>>();
        k_scatter<<<(int)((ng * 16 + 255) / 256), 256>>>();
    }
    k_final<<<(N_NODES * 16 + 255) / 256, 256>>>(bias, out);
}

// round 11
// speedup vs baseline: 1.3107x; 1.1519x over previous
#include <cuda_runtime.h>
#include <cuda_bf16.h>
#include <cuda_fp16.h>
#include <cstdint>

#define N_NODES 50000
#define E_EDGES 800000
#define EN_TOT  (E_EDGES + N_NODES)
#define IN_CH   256
#define OUT_CH  64
#define HEADS   4
#define HC      256
#define NEG_SLOPE 0.2f
#define MBLK    391            // ceil(50000/128)
#define SBLK    196            // ceil(50000/256)
#define ECHUNK  8              // edges per run-length group

// ---------------- device scratch ---------------------------------------------
__device__ uint4    g_Af[MBLK * 8192];      // A frags [mb][kc8][hl2][ks2][mt8][lane32]
__device__ uint4    g_Bf[5 * 4096];         // B frags [nb5][kc8][ks2][nt8][lane32]
__device__ __half2  g_outh[(size_t)N_NODES * 128];   // xw as fp16 [N][128 half2]
__device__ float    g_res[(size_t)N_NODES * OUT_CH]; // residual fp32
__device__ float    g_alog[N_NODES * 8];    // a_src[4] | a_dst[4]
__device__ float    g_den[N_NODES * HEADS];
__device__ float4   g_ew[EN_TOT];           // per-edge exp(alpha) per head
__device__ float    g_acc[(size_t)N_NODES * OUT_CH];
__device__ int      g_cnt[N_NODES];
__device__ int      g_bsum[SBLK];
__device__ int2     g_edges[EN_TOT];        // DST-sorted (s,d)
__device__ int      g_is64;

// ---------------- helpers ----------------------------------------------------
__device__ __forceinline__ int edge_at(const void* ei, int is64, long long idx) {
    return is64 ? (int)((const long long*)ei)[idx] : ((const int*)ei)[idx];
}
__device__ __forceinline__ float lrelu(float a) {
    return (a > 0.f) ? a : NEG_SLOPE * a;
}
__device__ __forceinline__ void cvt_hl(float x, float y, uint32_t& h, uint32_t& l) {
    __nv_bfloat162 hb = __floats2bfloat162_rn(x, y);
    float2 hf = __bfloat1622float2(hb);
    __nv_bfloat162 lb = __floats2bfloat162_rn(x - hf.x, y - hf.y);
    h = *(uint32_t*)&hb;
    l = *(uint32_t*)&lb;
}
#define MMA_BF16(d, a, b0, b1)                                                \
    asm volatile(                                                             \
        "mma.sync.aligned.m16n8k16.row.col.f32.bf16.bf16.f32 "                \
        "{%0,%1,%2,%3}, {%4,%5,%6,%7}, {%8,%9}, {%0,%1,%2,%3};"               \
        : "+f"(d[0]), "+f"(d[1]), "+f"(d[2]), "+f"(d[3])                      \
        : "r"(a.x), "r"(a.y), "r"(a.z), "r"(a.w), "r"(b0), "r"(b1))
#define REDV4(p, v)                                                           \
    asm volatile("red.global.add.v4.f32 [%0], {%1,%2,%3,%4};"                 \
                 :: "l"(p), "f"((v).x), "f"((v).y), "f"((v).z), "f"((v).w)    \
                 : "memory")

// ---------------- k_detect ----------------------------------------------------
__global__ void k_detect(const unsigned* __restrict__ ei_words) {
    __shared__ unsigned s_or;
    if (threadIdx.x == 0) s_or = 0;
    __syncthreads();
    unsigned v = 0;
    for (int i = threadIdx.x; i < 4096; i += blockDim.x)
        v |= ei_words[2 * i + 1];
    if (v) atomicOr(&s_or, 1u);
    __syncthreads();
    if (threadIdx.x == 0) g_is64 = (s_or == 0) ? 1 : 0;
}

// ---------------- k_init -------------------------------------------------------
__global__ void k_init() {
    long long idx = blockIdx.x * (long long)blockDim.x + threadIdx.x;
    long long stride = (long long)gridDim.x * blockDim.x;
    long long nacc4 = (long long)N_NODES * OUT_CH / 4;
    float4 z = make_float4(0.f, 0.f, 0.f, 0.f);
    for (long long i = idx; i < nacc4; i += stride) ((float4*)g_acc)[i] = z;
    for (long long i = idx; i < (long long)N_NODES * HEADS; i += stride)
        g_den[i] = 0.f;
    for (long long i = idx; i < N_NODES; i += stride) g_cnt[i] = 0;
}

// ---------------- counting sort by DST -----------------------------------------
__global__ void k_hist(const void* __restrict__ ei) {
    int is64 = g_is64;
    int e = blockIdx.x * blockDim.x + threadIdx.x;
    if (e >= EN_TOT) return;
    int d = (e < E_EDGES) ? edge_at(ei, is64, E_EDGES + e) : e - E_EDGES;
    atomicAdd(&g_cnt[d], 1);
}

__global__ void k_scanA() {
    __shared__ int sh[256];
    int t = threadIdx.x;
    int idx = blockIdx.x * 256 + t;
    int v = (idx < N_NODES) ? g_cnt[idx] : 0;
    sh[t] = v;
    __syncthreads();
#pragma unroll
    for (int off = 1; off < 256; off <<= 1) {
        int u = (t >= off) ? sh[t - off] : 0;
        __syncthreads();
        sh[t] += u;
        __syncthreads();
    }
    if (idx < N_NODES) g_cnt[idx] = sh[t] - v;
    if (t == 255) g_bsum[blockIdx.x] = sh[255];
}

__global__ void k_scanB() {
    __shared__ int sh[256];
    int t = threadIdx.x;
    int v = (t < SBLK) ? g_bsum[t] : 0;
    sh[t] = v;
    __syncthreads();
#pragma unroll
    for (int off = 1; off < 256; off <<= 1) {
        int u = (t >= off) ? sh[t - off] : 0;
        __syncthreads();
        sh[t] += u;
        __syncthreads();
    }
    if (t < SBLK) g_bsum[t] = sh[t] - v;
}

__global__ void k_scanC() {
    int idx = blockIdx.x * blockDim.x + threadIdx.x;
    if (idx < N_NODES) g_cnt[idx] += g_bsum[idx >> 8];
}

__global__ void k_place(const void* __restrict__ ei) {
    int is64 = g_is64;
    int e = blockIdx.x * blockDim.x + threadIdx.x;
    if (e >= EN_TOT) return;
    int s, d;
    if (e < E_EDGES) {
        s = edge_at(ei, is64, e);
        d = edge_at(ei, is64, E_EDGES + e);
    } else {
        s = d = e - E_EDGES;
    }
    int pos = atomicAdd(&g_cnt[d], 1);
    g_edges[pos] = make_int2(s, d);
}

// ---------------- k_prep: X -> bf16 hi/lo fragments ----------------------------
__global__ void k_prep(const float* __restrict__ X) {
    int t = blockIdx.x * blockDim.x + threadIdx.x;
    if (t >= MBLK * 4096) return;
    int lane = t & 31;
    int mt = (t >> 5) & 7;
    int ks = (t >> 8) & 1;
    int kc = (t >> 9) & 7;
    int mb = t >> 12;

    int r0 = mb * 128 + mt * 16 + (lane >> 2);
    int tt = lane & 3;
    int k0 = kc * 32 + (ks * 8 + tt) * 2;

    float2 v[4];
    v[0] = (r0 < N_NODES) ? *(const float2*)(X + (size_t)r0 * IN_CH + k0)
                          : make_float2(0.f, 0.f);
    v[1] = (r0 + 8 < N_NODES) ? *(const float2*)(X + (size_t)(r0 + 8) * IN_CH + k0)
                              : make_float2(0.f, 0.f);
    v[2] = (r0 < N_NODES) ? *(const float2*)(X + (size_t)r0 * IN_CH + k0 + 8)
                          : make_float2(0.f, 0.f);
    v[3] = (r0 + 8 < N_NODES) ? *(const float2*)(X + (size_t)(r0 + 8) * IN_CH + k0 + 8)
                              : make_float2(0.f, 0.f);
    uint4 hv, lv;
    cvt_hl(v[0].x, v[0].y, hv.x, lv.x);
    cvt_hl(v[1].x, v[1].y, hv.y, lv.y);
    cvt_hl(v[2].x, v[2].y, hv.z, lv.z);
    cvt_hl(v[3].x, v[3].y, hv.w, lv.w);

    int base = mb * 8192 + kc * 1024 + ks * 256 + mt * 32 + lane;
    g_Af[base] = hv;
    g_Af[base + 512] = lv;
}

// ---------------- k_packB ------------------------------------------------------
__global__ void k_packB(const float* __restrict__ W, const float* __restrict__ Wr) {
    int t = blockIdx.x * blockDim.x + threadIdx.x;
    if (t >= 5 * 4096) return;
    int lane = t & 31;
    int nt = (t >> 5) & 7;
    int ks = (t >> 8) & 1;
    int kc = (t >> 9) & 7;
    int nb = t >> 12;

    int col = nb * 64 + nt * 8 + (lane >> 2);
    int tt = lane & 3;
    int k0 = kc * 32 + ks * 16 + tt * 2;

    float b00, b01, b10, b11;
    if (col < HC) {
        b00 = W[(k0) * HC + col];     b01 = W[(k0 + 1) * HC + col];
        b10 = W[(k0 + 8) * HC + col]; b11 = W[(k0 + 9) * HC + col];
    } else {
        int c = col - HC;
        b00 = Wr[(k0) * OUT_CH + c];     b01 = Wr[(k0 + 1) * OUT_CH + c];
        b10 = Wr[(k0 + 8) * OUT_CH + c]; b11 = Wr[(k0 + 9) * OUT_CH + c];
    }
    uint4 o;
    cvt_hl(b00, b01, o.x, o.z);
    cvt_hl(b10, b11, o.y, o.w);
    g_Bf[nb * 4096 + kc * 512 + ks * 256 + nt * 32 + lane] = o;
}

// ---------------- k_gemm: mma.sync + fused logits + fp16 xw out ---------------
__global__ __launch_bounds__(256) void k_gemm(const float* __restrict__ att_src,
                                              const float* __restrict__ att_dst) {
    __shared__ float sAttS[64], sAttD[64], sA[128], sD[128];
    int tid = threadIdx.x;
    int lane = tid & 31;
    int wid = tid >> 5;
    int mrow = wid >> 1;
    int ncol = wid & 1;
    int mb = blockIdx.y;
    int nb = blockIdx.x;

    if (nb < 4) {
        if (tid < 64) {
            sAttS[tid] = att_src[nb * 64 + tid];
            sAttD[tid] = att_dst[nb * 64 + tid];
        }
        if (tid >= 64 && tid < 192) {
            sA[tid - 64] = 0.f;
            sD[tid - 64] = 0.f;
        }
        __syncthreads();
    }

    float acc[2][4][4];
#pragma unroll
    for (int i = 0; i < 2; i++)
#pragma unroll
        for (int j = 0; j < 4; j++)
#pragma unroll
            for (int q = 0; q < 4; q++) acc[i][j][q] = 0.f;

    const uint4* Ab = g_Af + mb * 8192;
    const uint4* Bb = g_Bf + nb * 4096;

#pragma unroll 1
    for (int kc = 0; kc < 8; kc++) {
        const uint4* Ak = Ab + kc * 1024;
        const uint4* Bk = Bb + kc * 512;
        uint4 ah[2][2], al[2][2];
#pragma unroll
        for (int ks = 0; ks < 2; ks++)
#pragma unroll
            for (int mt = 0; mt < 2; mt++) {
                int m = mrow * 2 + mt;
                ah[ks][mt] = Ak[ks * 256 + m * 32 + lane];
                al[ks][mt] = Ak[512 + ks * 256 + m * 32 + lane];
            }
#pragma unroll
        for (int ks = 0; ks < 2; ks++)
#pragma unroll
            for (int j = 0; j < 4; j++) {
                uint4 bv = Bk[ks * 256 + (ncol * 4 + j) * 32 + lane];
#pragma unroll
                for (int mt = 0; mt < 2; mt++) {
                    MMA_BF16(acc[mt][j], ah[ks][mt], bv.x, bv.y);
                    MMA_BF16(acc[mt][j], ah[ks][mt], bv.z, bv.w);
                    MMA_BF16(acc[mt][j], al[ks][mt], bv.x, bv.y);
                }
            }
    }

    // epilogue: xw -> fp16 g_outh (nb<4); residual -> fp32 g_res (nb==4)
#pragma unroll
    for (int mt = 0; mt < 2; mt++)
#pragma unroll
        for (int nt = 0; nt < 4; nt++) {
            int row0 = mb * 128 + (mrow * 2 + mt) * 16 + (lane >> 2);
            int colg = (ncol * 4 + nt) * 8 + (lane & 3) * 2;   // 0..63
            if (nb < 4) {
                int hidx = (nb * 64 + colg) >> 1;
                if (row0 < N_NODES)
                    g_outh[(size_t)row0 * 128 + hidx] =
                        __floats2half2_rn(acc[mt][nt][0], acc[mt][nt][1]);
                if (row0 + 8 < N_NODES)
                    g_outh[(size_t)(row0 + 8) * 128 + hidx] =
                        __floats2half2_rn(acc[mt][nt][2], acc[mt][nt][3]);
            } else {
                float* p = g_res + (size_t)row0 * OUT_CH + colg;
                if (row0 < N_NODES)
                    *(float2*)p = make_float2(acc[mt][nt][0], acc[mt][nt][1]);
                if (row0 + 8 < N_NODES)
                    *(float2*)(p + 8 * OUT_CH) =
                        make_float2(acc[mt][nt][2], acc[mt][nt][3]);
            }
        }

    if (nb < 4) {
#pragma unroll
        for (int mt = 0; mt < 2; mt++) {
            float s0 = 0.f, d0 = 0.f, s1 = 0.f, d1 = 0.f;
#pragma unroll
            for (int nt = 0; nt < 4; nt++) {
                int cl = (ncol * 4 + nt) * 8 + (lane & 3) * 2;
                float a0 = sAttS[cl], a1 = sAttS[cl + 1];
                float b0 = sAttD[cl], b1 = sAttD[cl + 1];
                s0 += acc[mt][nt][0] * a0 + acc[mt][nt][1] * a1;
                s1 += acc[mt][nt][2] * a0 + acc[mt][nt][3] * a1;
                d0 += acc[mt][nt][0] * b0 + acc[mt][nt][1] * b1;
                d1 += acc[mt][nt][2] * b0 + acc[mt][nt][3] * b1;
            }
#pragma unroll
            for (int o = 1; o < 4; o <<= 1) {
                s0 += __shfl_xor_sync(0xffffffffu, s0, o);
                s1 += __shfl_xor_sync(0xffffffffu, s1, o);
                d0 += __shfl_xor_sync(0xffffffffu, d0, o);
                d1 += __shfl_xor_sync(0xffffffffu, d1, o);
            }
            if ((lane & 3) == 0) {
                int r = (mrow * 2 + mt) * 16 + (lane >> 2);
                atomicAdd(&sA[r], s0);
                atomicAdd(&sD[r], d0);
                atomicAdd(&sA[r + 8], s1);
                atomicAdd(&sD[r + 8], d1);
            }
        }
        __syncthreads();
        for (int r = tid; r < 128; r += 256) {
            int n = mb * 128 + r;
            if (n < N_NODES) {
                g_alog[n * 8 + nb] = sA[r];
                g_alog[n * 8 + 4 + nb] = sD[r];
            }
        }
    }
}

// ---------------- k_sum: 1 thread = ECHUNK dst-sorted edges --------------------
__global__ void k_sum() {
    long long g = blockIdx.x * (long long)blockDim.x + threadIdx.x;
    long long e0 = g * ECHUNK;
    if (e0 >= EN_TOT) return;
    float4 acc = make_float4(0.f, 0.f, 0.f, 0.f);
    int dprev = -1;
#pragma unroll
    for (int i = 0; i < ECHUNK; i++) {
        long long e = e0 + i;
        if (e >= EN_TOT) break;
        int2 ed = g_edges[e];
        float4 as = *(const float4*)(g_alog + ed.x * 8);
        float4 ad = *(const float4*)(g_alog + ed.y * 8 + 4);
        float4 ex;
        ex.x = __expf(lrelu(as.x + ad.x));
        ex.y = __expf(lrelu(as.y + ad.y));
        ex.z = __expf(lrelu(as.z + ad.z));
        ex.w = __expf(lrelu(as.w + ad.w));
        g_ew[e] = ex;
        if (ed.y != dprev) {
            if (dprev >= 0) REDV4(g_den + dprev * 4, acc);
            acc = ex;
            dprev = ed.y;
        } else {
            acc.x += ex.x; acc.y += ex.y; acc.z += ex.z; acc.w += ex.w;
        }
    }
    if (dprev >= 0) REDV4(g_den + dprev * 4, acc);
}

// ---------------- k_invden -----------------------------------------------------
__global__ void k_invden() {
    int i = blockIdx.x * blockDim.x + threadIdx.x;
    if (i < N_NODES * HEADS) g_den[i] = 1.0f / g_den[i];
}

// ---------------- k_scatter: fp16 gather, 16 lanes x ECHUNK edges --------------
__global__ void k_scatter() {
    int lane = threadIdx.x & 31;
    int sub = lane & 15;
    long long grp = ((long long)blockIdx.x * blockDim.x + threadIdx.x) >> 4;
    long long e0 = grp * ECHUNK;
    if (e0 >= EN_TOT) return;
    int c0 = sub * 4;

    float4 acc = make_float4(0.f, 0.f, 0.f, 0.f);
    int dprev = -1;
#pragma unroll
    for (int i = 0; i < ECHUNK; i++) {
        long long e = e0 + i;
        if (e >= EN_TOT) break;
        int2 ed = g_edges[e];
        float4 w = g_ew[e];
        float4 dn = *(const float4*)(g_den + ed.y * 4);
        float wh[4] = {w.x * dn.x, w.y * dn.y, w.z * dn.z, w.w * dn.w};

        if (ed.y != dprev) {
            if (dprev >= 0)
                REDV4(g_acc + (size_t)dprev * OUT_CH + c0, acc);
            acc = make_float4(0.f, 0.f, 0.f, 0.f);
            dprev = ed.y;
        }
#pragma unroll
        for (int h = 0; h < 4; h++) {
            uint2 raw = *(const uint2*)(g_outh + (size_t)ed.x * 128 + h * 32 + sub * 2);
            float2 a = __half22float2(*(__half2*)&raw.x);
            float2 b = __half22float2(*(__half2*)&raw.y);
            acc.x = fmaf(wh[h], a.x, acc.x);
            acc.y = fmaf(wh[h], a.y, acc.y);
            acc.z = fmaf(wh[h], b.x, acc.z);
            acc.w = fmaf(wh[h], b.y, acc.w);
        }
    }
    if (dprev >= 0)
        REDV4(g_acc + (size_t)dprev * OUT_CH + c0, acc);
}

// ---------------- k_final ------------------------------------------------------
__global__ void k_final(const float* __restrict__ bias, float* __restrict__ out) {
    int i = blockIdx.x * blockDim.x + threadIdx.x;
    if (i >= N_NODES * 16) return;
    int n = i >> 4;
    int c = (i & 15) * 4;
    float4 a = *(const float4*)(g_acc + (size_t)n * OUT_CH + c);
    float4 b = *(const float4*)(bias + c);
    float4 r = *(const float4*)(g_res + (size_t)n * OUT_CH + c);
    float4 o;
    o.x = fmaxf(0.f, 0.25f * a.x + b.x + r.x);
    o.y = fmaxf(0.f, 0.25f * a.y + b.y + r.y);
    o.z = fmaxf(0.f, 0.25f * a.z + b.z + r.z);
    o.w = fmaxf(0.f, 0.25f * a.w + b.w + r.w);
    *(float4*)(out + (size_t)n * OUT_CH + c) = o;
}

// ---------------- launch -------------------------------------------------------
extern "C" void kernel_launch(void* const* d_in, const int* in_sizes, int n_in,
                              void* d_out, int out_size) {
    const float* x       = (const float*)d_in[0];
    const void*  ei      = d_in[1];
    const float* W       = (const float*)d_in[2];
    const float* att_src = (const float*)d_in[3];
    const float* att_dst = (const float*)d_in[4];
    const float* bias    = (const float*)d_in[5];
    const float* W_res   = (const float*)d_in[6];
    float* out = (float*)d_out;

    k_detect<<<1, 256>>>((const unsigned*)ei);
    k_init<<<1024, 256>>>();
    k_hist<<<(EN_TOT + 255) / 256, 256>>>(ei);
    k_scanA<<<SBLK, 256>>>();
    k_scanB<<<1, 256>>>();
    k_scanC<<<SBLK, 256>>>();
    k_place<<<(EN_TOT + 255) / 256, 256>>>(ei);
    k_prep<<<(MBLK * 4096 + 255) / 256, 256>>>(x);
    k_packB<<<(5 * 4096 + 255) / 256, 256>>>(W, W_res);
    dim3 ggrid(5, MBLK);
    k_gemm<<<ggrid, 256>>>(att_src, att_dst);
    {
        long long ng = (EN_TOT + ECHUNK - 1) / ECHUNK;
        k_sum<<<(int)((ng + 255) / 256), 256>>>();
        k_invden<<<(N_NODES * HEADS + 255) / 256, 256>>>();
        k_scatter<<<(int)((ng * 16 + 255) / 256), 256>>>();
    }
    k_final<<<(N_NODES * 16 + 255) / 256, 256>>>(bias, out);
}

// round 12
// speedup vs baseline: 1.4544x; 1.1097x over previous
#include <cuda_runtime.h>
#include <cuda_bf16.h>
#include <cuda_fp16.h>
#include <cstdint>

#define N_NODES 50000
#define E_EDGES 800000
#define EN_TOT  (E_EDGES + N_NODES)
#define IN_CH   256
#define OUT_CH  64
#define HEADS   4
#define HC      256
#define NEG_SLOPE 0.2f
#define MBLK    391            // ceil(50000/128)
#define SBLK    196            // ceil(50000/256)
#define ECHUNK  8              // edges per group in k_sum
#define SCHUNK  16             // edges per group in k_scatter

// ---------------- device scratch ---------------------------------------------
__device__ uint4    g_Af[MBLK * 8192];      // A frags [mb][kc8][hl2][ks2][mt8][lane32]
__device__ uint4    g_Bf[5 * 4096];         // B frags [nb5][kc8][ks2][nt8][lane32]
__device__ __half2  g_outh[(size_t)N_NODES * 128];   // xw fp16 [N][128 half2]
__device__ float    g_res[(size_t)N_NODES * OUT_CH]; // residual fp32
__device__ float    g_alog[N_NODES * 8];
__device__ float    g_den[N_NODES * HEADS];
__device__ float4   g_ew[EN_TOT];
__device__ float    g_acc[(size_t)N_NODES * OUT_CH];
__device__ int      g_cnt[N_NODES];
__device__ int      g_bsum[SBLK];
__device__ int2     g_edges[EN_TOT];        // DST-sorted (s,d)
__device__ int      g_is64;

// ---------------- helpers ----------------------------------------------------
__device__ __forceinline__ int edge_at(const void* ei, int is64, long long idx) {
    return is64 ? (int)((const long long*)ei)[idx] : ((const int*)ei)[idx];
}
__device__ __forceinline__ float lrelu(float a) {
    return (a > 0.f) ? a : NEG_SLOPE * a;
}
__device__ __forceinline__ void cvt_hl(float x, float y, uint32_t& h, uint32_t& l) {
    __nv_bfloat162 hb = __floats2bfloat162_rn(x, y);
    float2 hf = __bfloat1622float2(hb);
    __nv_bfloat162 lb = __floats2bfloat162_rn(x - hf.x, y - hf.y);
    h = *(uint32_t*)&hb;
    l = *(uint32_t*)&lb;
}
#define MMA_BF16(d, a, b0, b1)                                                \
    asm volatile(                                                             \
        "mma.sync.aligned.m16n8k16.row.col.f32.bf16.bf16.f32 "                \
        "{%0,%1,%2,%3}, {%4,%5,%6,%7}, {%8,%9}, {%0,%1,%2,%3};"               \
        : "+f"(d[0]), "+f"(d[1]), "+f"(d[2]), "+f"(d[3])                      \
        : "r"(a.x), "r"(a.y), "r"(a.z), "r"(a.w), "r"(b0), "r"(b1))
#define REDV4(p, v)                                                           \
    asm volatile("red.global.add.v4.f32 [%0], {%1,%2,%3,%4};"                 \
                 :: "l"(p), "f"((v).x), "f"((v).y), "f"((v).z), "f"((v).w)    \
                 : "memory")
#define CP16(saddr, gptr)                                                     \
    asm volatile("cp.async.cg.shared.global [%0], [%1], 16;"                  \
                 :: "r"(saddr), "l"(gptr) : "memory")
#define CP_COMMIT() asm volatile("cp.async.commit_group;" ::: "memory")
#define CP_WAIT1()  asm volatile("cp.async.wait_group 1;" ::: "memory")
#define CP_WAIT0()  asm volatile("cp.async.wait_group 0;" ::: "memory")

// ---------------- k_detect ----------------------------------------------------
__global__ void k_detect(const unsigned* __restrict__ ei_words) {
    __shared__ unsigned s_or;
    if (threadIdx.x == 0) s_or = 0;
    __syncthreads();
    unsigned v = 0;
    for (int i = threadIdx.x; i < 4096; i += blockDim.x)
        v |= ei_words[2 * i + 1];
    if (v) atomicOr(&s_or, 1u);
    __syncthreads();
    if (threadIdx.x == 0) g_is64 = (s_or == 0) ? 1 : 0;
}

// ---------------- k_init -------------------------------------------------------
__global__ void k_init() {
    long long idx = blockIdx.x * (long long)blockDim.x + threadIdx.x;
    long long stride = (long long)gridDim.x * blockDim.x;
    long long nacc4 = (long long)N_NODES * OUT_CH / 4;
    float4 z = make_float4(0.f, 0.f, 0.f, 0.f);
    for (long long i = idx; i < nacc4; i += stride) ((float4*)g_acc)[i] = z;
    for (long long i = idx; i < (long long)N_NODES * HEADS; i += stride)
        g_den[i] = 0.f;
    for (long long i = idx; i < N_NODES; i += stride) g_cnt[i] = 0;
}

// ---------------- counting sort by DST -----------------------------------------
__global__ void k_hist(const void* __restrict__ ei) {
    int is64 = g_is64;
    int e = blockIdx.x * blockDim.x + threadIdx.x;
    if (e >= EN_TOT) return;
    int d = (e < E_EDGES) ? edge_at(ei, is64, E_EDGES + e) : e - E_EDGES;
    atomicAdd(&g_cnt[d], 1);
}

__global__ void k_scanA() {
    __shared__ int sh[256];
    int t = threadIdx.x;
    int idx = blockIdx.x * 256 + t;
    int v = (idx < N_NODES) ? g_cnt[idx] : 0;
    sh[t] = v;
    __syncthreads();
#pragma unroll
    for (int off = 1; off < 256; off <<= 1) {
        int u = (t >= off) ? sh[t - off] : 0;
        __syncthreads();
        sh[t] += u;
        __syncthreads();
    }
    if (idx < N_NODES) g_cnt[idx] = sh[t] - v;
    if (t == 255) g_bsum[blockIdx.x] = sh[255];
}

__global__ void k_scanB() {
    __shared__ int sh[256];
    int t = threadIdx.x;
    int v = (t < SBLK) ? g_bsum[t] : 0;
    sh[t] = v;
    __syncthreads();
#pragma unroll
    for (int off = 1; off < 256; off <<= 1) {
        int u = (t >= off) ? sh[t - off] : 0;
        __syncthreads();
        sh[t] += u;
        __syncthreads();
    }
    if (t < SBLK) g_bsum[t] = sh[t] - v;
}

__global__ void k_scanC() {
    int idx = blockIdx.x * blockDim.x + threadIdx.x;
    if (idx < N_NODES) g_cnt[idx] += g_bsum[idx >> 8];
}

__global__ void k_place(const void* __restrict__ ei) {
    int is64 = g_is64;
    int e = blockIdx.x * blockDim.x + threadIdx.x;
    if (e >= EN_TOT) return;
    int s, d;
    if (e < E_EDGES) {
        s = edge_at(ei, is64, e);
        d = edge_at(ei, is64, E_EDGES + e);
    } else {
        s = d = e - E_EDGES;
    }
    int pos = atomicAdd(&g_cnt[d], 1);
    g_edges[pos] = make_int2(s, d);
}

// ---------------- k_prep: X -> bf16 hi/lo fragments ----------------------------
__global__ void k_prep(const float* __restrict__ X) {
    int t = blockIdx.x * blockDim.x + threadIdx.x;
    if (t >= MBLK * 4096) return;
    int lane = t & 31;
    int mt = (t >> 5) & 7;
    int ks = (t >> 8) & 1;
    int kc = (t >> 9) & 7;
    int mb = t >> 12;

    int r0 = mb * 128 + mt * 16 + (lane >> 2);
    int tt = lane & 3;
    int k0 = kc * 32 + (ks * 8 + tt) * 2;

    float2 v[4];
    v[0] = (r0 < N_NODES) ? *(const float2*)(X + (size_t)r0 * IN_CH + k0)
                          : make_float2(0.f, 0.f);
    v[1] = (r0 + 8 < N_NODES) ? *(const float2*)(X + (size_t)(r0 + 8) * IN_CH + k0)
                              : make_float2(0.f, 0.f);
    v[2] = (r0 < N_NODES) ? *(const float2*)(X + (size_t)r0 * IN_CH + k0 + 8)
                          : make_float2(0.f, 0.f);
    v[3] = (r0 + 8 < N_NODES) ? *(const float2*)(X + (size_t)(r0 + 8) * IN_CH + k0 + 8)
                              : make_float2(0.f, 0.f);
    uint4 hv, lv;
    cvt_hl(v[0].x, v[0].y, hv.x, lv.x);
    cvt_hl(v[1].x, v[1].y, hv.y, lv.y);
    cvt_hl(v[2].x, v[2].y, hv.z, lv.z);
    cvt_hl(v[3].x, v[3].y, hv.w, lv.w);

    int base = mb * 8192 + kc * 1024 + ks * 256 + mt * 32 + lane;
    g_Af[base] = hv;
    g_Af[base + 512] = lv;
}

// ---------------- k_packB ------------------------------------------------------
__global__ void k_packB(const float* __restrict__ W, const float* __restrict__ Wr) {
    int t = blockIdx.x * blockDim.x + threadIdx.x;
    if (t >= 5 * 4096) return;
    int lane = t & 31;
    int nt = (t >> 5) & 7;
    int ks = (t >> 8) & 1;
    int kc = (t >> 9) & 7;
    int nb = t >> 12;

    int col = nb * 64 + nt * 8 + (lane >> 2);
    int tt = lane & 3;
    int k0 = kc * 32 + ks * 16 + tt * 2;

    float b00, b01, b10, b11;
    if (col < HC) {
        b00 = W[(k0) * HC + col];     b01 = W[(k0 + 1) * HC + col];
        b10 = W[(k0 + 8) * HC + col]; b11 = W[(k0 + 9) * HC + col];
    } else {
        int c = col - HC;
        b00 = Wr[(k0) * OUT_CH + c];     b01 = Wr[(k0 + 1) * OUT_CH + c];
        b10 = Wr[(k0 + 8) * OUT_CH + c]; b11 = Wr[(k0 + 9) * OUT_CH + c];
    }
    uint4 o;
    cvt_hl(b00, b01, o.x, o.z);
    cvt_hl(b10, b11, o.y, o.w);
    g_Bf[nb * 4096 + kc * 512 + ks * 256 + nt * 32 + lane] = o;
}

// ---------------- k_gemm: cp.async 2-stage pipeline + fused logits ------------
// dyn smem: 2 stages x (A 1024 uint4 | B 512 uint4) = 49152 B
__global__ __launch_bounds__(256) void k_gemm(const float* __restrict__ att_src,
                                              const float* __restrict__ att_dst) {
    extern __shared__ uint4 sbuf[];
    __shared__ float sAttS[64], sAttD[64], sA[128], sD[128];
    int tid = threadIdx.x;
    int lane = tid & 31;
    int wid = tid >> 5;
    int mrow = wid >> 1;
    int ncol = wid & 1;
    int mb = blockIdx.y;
    int nb = blockIdx.x;

    if (nb < 4) {
        if (tid < 64) {
            sAttS[tid] = att_src[nb * 64 + tid];
            sAttD[tid] = att_dst[nb * 64 + tid];
        }
        if (tid >= 64 && tid < 192) {
            sA[tid - 64] = 0.f;
            sD[tid - 64] = 0.f;
        }
    }

    const uint4* Ab = g_Af + mb * 8192;
    const uint4* Bb = g_Bf + nb * 4096;
    uint32_t sb32 = (uint32_t)__cvta_generic_to_shared(sbuf);

    // stage issue: copy kc's 1024 A + 512 B uint4 into stage buffer
    auto issue = [&](int kc, int stage) {
        uint32_t sa = sb32 + (stage * 1536) * 16;
        const uint4* gA = Ab + kc * 1024;
#pragma unroll
        for (int i = 0; i < 4; i++)
            CP16(sa + (tid + 256 * i) * 16, gA + tid + 256 * i);
        uint32_t sbB = sb32 + (stage * 1536 + 1024) * 16;
        const uint4* gB = Bb + kc * 512;
#pragma unroll
        for (int i = 0; i < 2; i++)
            CP16(sbB + (tid + 256 * i) * 16, gB + tid + 256 * i);
        CP_COMMIT();
    };

    float acc[2][4][4];
#pragma unroll
    for (int i = 0; i < 2; i++)
#pragma unroll
        for (int j = 0; j < 4; j++)
#pragma unroll
            for (int q = 0; q < 4; q++) acc[i][j][q] = 0.f;

    issue(0, 0);

#pragma unroll 1
    for (int kc = 0; kc < 8; kc++) {
        if (kc < 7) {
            issue(kc + 1, (kc + 1) & 1);
            CP_WAIT1();
        } else {
            CP_WAIT0();
        }
        __syncthreads();
        const uint4* bufA = sbuf + (kc & 1) * 1536;
        const uint4* bufB = bufA + 1024;
        uint4 ah[2][2], al[2][2];
#pragma unroll
        for (int ks = 0; ks < 2; ks++)
#pragma unroll
            for (int mt = 0; mt < 2; mt++) {
                int m = mrow * 2 + mt;
                ah[ks][mt] = bufA[ks * 256 + m * 32 + lane];
                al[ks][mt] = bufA[512 + ks * 256 + m * 32 + lane];
            }
#pragma unroll
        for (int ks = 0; ks < 2; ks++)
#pragma unroll
            for (int j = 0; j < 4; j++) {
                uint4 bv = bufB[ks * 256 + (ncol * 4 + j) * 32 + lane];
#pragma unroll
                for (int mt = 0; mt < 2; mt++) {
                    MMA_BF16(acc[mt][j], ah[ks][mt], bv.x, bv.y);
                    MMA_BF16(acc[mt][j], ah[ks][mt], bv.z, bv.w);
                    MMA_BF16(acc[mt][j], al[ks][mt], bv.x, bv.y);
                }
            }
        __syncthreads();
    }

    // epilogue: xw -> fp16 g_outh (nb<4); residual -> fp32 g_res (nb==4)
#pragma unroll
    for (int mt = 0; mt < 2; mt++)
#pragma unroll
        for (int nt = 0; nt < 4; nt++) {
            int row0 = mb * 128 + (mrow * 2 + mt) * 16 + (lane >> 2);
            int colg = (ncol * 4 + nt) * 8 + (lane & 3) * 2;   // 0..63
            if (nb < 4) {
                int hidx = (nb * 64 + colg) >> 1;
                if (row0 < N_NODES)
                    g_outh[(size_t)row0 * 128 + hidx] =
                        __floats2half2_rn(acc[mt][nt][0], acc[mt][nt][1]);
                if (row0 + 8 < N_NODES)
                    g_outh[(size_t)(row0 + 8) * 128 + hidx] =
                        __floats2half2_rn(acc[mt][nt][2], acc[mt][nt][3]);
            } else {
                float* p = g_res + (size_t)row0 * OUT_CH + colg;
                if (row0 < N_NODES)
                    *(float2*)p = make_float2(acc[mt][nt][0], acc[mt][nt][1]);
                if (row0 + 8 < N_NODES)
                    *(float2*)(p + 8 * OUT_CH) =
                        make_float2(acc[mt][nt][2], acc[mt][nt][3]);
            }
        }

    if (nb < 4) {
#pragma unroll
        for (int mt = 0; mt < 2; mt++) {
            float s0 = 0.f, d0 = 0.f, s1 = 0.f, d1 = 0.f;
#pragma unroll
            for (int nt = 0; nt < 4; nt++) {
                int cl = (ncol * 4 + nt) * 8 + (lane & 3) * 2;
                float a0 = sAttS[cl], a1 = sAttS[cl + 1];
                float b0 = sAttD[cl], b1 = sAttD[cl + 1];
                s0 += acc[mt][nt][0] * a0 + acc[mt][nt][1] * a1;
                s1 += acc[mt][nt][2] * a0 + acc[mt][nt][3] * a1;
                d0 += acc[mt][nt][0] * b0 + acc[mt][nt][1] * b1;
                d1 += acc[mt][nt][2] * b0 + acc[mt][nt][3] * b1;
            }
#pragma unroll
            for (int o = 1; o < 4; o <<= 1) {
                s0 += __shfl_xor_sync(0xffffffffu, s0, o);
                s1 += __shfl_xor_sync(0xffffffffu, s1, o);
                d0 += __shfl_xor_sync(0xffffffffu, d0, o);
                d1 += __shfl_xor_sync(0xffffffffu, d1, o);
            }
            if ((lane & 3) == 0) {
                int r = (mrow * 2 + mt) * 16 + (lane >> 2);
                atomicAdd(&sA[r], s0);
                atomicAdd(&sD[r], d0);
                atomicAdd(&sA[r + 8], s1);
                atomicAdd(&sD[r + 8], d1);
            }
        }
        __syncthreads();
        for (int r = tid; r < 128; r += 256) {
            int n = mb * 128 + r;
            if (n < N_NODES) {
                g_alog[n * 8 + nb] = sA[r];
                g_alog[n * 8 + 4 + nb] = sD[r];
            }
        }
    }
}

// ---------------- k_sum: 1 thread = ECHUNK dst-sorted edges --------------------
__global__ void k_sum() {
    long long g = blockIdx.x * (long long)blockDim.x + threadIdx.x;
    long long e0 = g * ECHUNK;
    if (e0 >= EN_TOT) return;
    float4 acc = make_float4(0.f, 0.f, 0.f, 0.f);
    int dprev = -1;
#pragma unroll
    for (int i = 0; i < ECHUNK; i++) {
        long long e = e0 + i;
        if (e >= EN_TOT) break;
        int2 ed = g_edges[e];
        float4 as = *(const float4*)(g_alog + ed.x * 8);
        float4 ad = *(const float4*)(g_alog + ed.y * 8 + 4);
        float4 ex;
        ex.x = __expf(lrelu(as.x + ad.x));
        ex.y = __expf(lrelu(as.y + ad.y));
        ex.z = __expf(lrelu(as.z + ad.z));
        ex.w = __expf(lrelu(as.w + ad.w));
        g_ew[e] = ex;
        if (ed.y != dprev) {
            if (dprev >= 0) REDV4(g_den + dprev * 4, acc);
            acc = ex;
            dprev = ed.y;
        } else {
            acc.x += ex.x; acc.y += ex.y; acc.z += ex.z; acc.w += ex.w;
        }
    }
    if (dprev >= 0) REDV4(g_den + dprev * 4, acc);
}

// ---------------- k_invden -----------------------------------------------------
__global__ void k_invden() {
    int i = blockIdx.x * blockDim.x + threadIdx.x;
    if (i < N_NODES * HEADS) g_den[i] = 1.0f / g_den[i];
}

// ---------------- k_scatter: fp16 gather, 16 lanes x SCHUNK edges --------------
__global__ void k_scatter() {
    int lane = threadIdx.x & 31;
    int sub = lane & 15;
    long long grp = ((long long)blockIdx.x * blockDim.x + threadIdx.x) >> 4;
    long long e0 = grp * SCHUNK;
    if (e0 >= EN_TOT) return;
    int c0 = sub * 4;

    float4 acc = make_float4(0.f, 0.f, 0.f, 0.f);
    int dprev = -1;
#pragma unroll
    for (int i = 0; i < SCHUNK; i++) {
        long long e = e0 + i;
        if (e >= EN_TOT) break;
        int2 ed = g_edges[e];
        float4 w = g_ew[e];
        float4 dn = *(const float4*)(g_den + ed.y * 4);
        float wh[4] = {w.x * dn.x, w.y * dn.y, w.z * dn.z, w.w * dn.w};

        if (ed.y != dprev) {
            if (dprev >= 0)
                REDV4(g_acc + (size_t)dprev * OUT_CH + c0, acc);
            acc = make_float4(0.f, 0.f, 0.f, 0.f);
            dprev = ed.y;
        }
#pragma unroll
        for (int h = 0; h < 4; h++) {
            uint2 raw = *(const uint2*)(g_outh + (size_t)ed.x * 128 + h * 32 + sub * 2);
            float2 a = __half22float2(*(__half2*)&raw.x);
            float2 b = __half22float2(*(__half2*)&raw.y);
            acc.x = fmaf(wh[h], a.x, acc.x);
            acc.y = fmaf(wh[h], a.y, acc.y);
            acc.z = fmaf(wh[h], b.x, acc.z);
            acc.w = fmaf(wh[h], b.y, acc.w);
        }
    }
    if (dprev >= 0)
        REDV4(g_acc + (size_t)dprev * OUT_CH + c0, acc);
}

// ---------------- k_final ------------------------------------------------------
__global__ void k_final(const float* __restrict__ bias, float* __restrict__ out) {
    int i = blockIdx.x * blockDim.x + threadIdx.x;
    if (i >= N_NODES * 16) return;
    int n = i >> 4;
    int c = (i & 15) * 4;
    float4 a = *(const float4*)(g_acc + (size_t)n * OUT_CH + c);
    float4 b = *(const float4*)(bias + c);
    float4 r = *(const float4*)(g_res + (size_t)n * OUT_CH + c);
    float4 o;
    o.x = fmaxf(0.f, 0.25f * a.x + b.x + r.x);
    o.y = fmaxf(0.f, 0.25f * a.y + b.y + r.y);
    o.z = fmaxf(0.f, 0.25f * a.z + b.z + r.z);
    o.w = fmaxf(0.f, 0.25f * a.w + b.w + r.w);
    *(float4*)(out + (size_t)n * OUT_CH + c) = o;
}

// ---------------- launch -------------------------------------------------------
extern "C" void kernel_launch(void* const* d_in, const int* in_sizes, int n_in,
                              void* d_out, int out_size) {
    const float* x       = (const float*)d_in[0];
    const void*  ei      = d_in[1];
    const float* W       = (const float*)d_in[2];
    const float* att_src = (const float*)d_in[3];
    const float* att_dst = (const float*)d_in[4];
    const float* bias    = (const float*)d_in[5];
    const float* W_res   = (const float*)d_in[6];
    float* out = (float*)d_out;

    const int GSMEM = 2 * 1536 * 16;   // 49152 B
    cudaFuncSetAttribute(k_gemm, cudaFuncAttributeMaxDynamicSharedMemorySize,
                         GSMEM);

    k_detect<<<1, 256>>>((const unsigned*)ei);
    k_init<<<1024, 256>>>();
    k_hist<<<(EN_TOT + 255) / 256, 256>>>(ei);
    k_scanA<<<SBLK, 256>>>();
    k_scanB<<<1, 256>>>();
    k_scanC<<<SBLK, 256>>>();
    k_place<<<(EN_TOT + 255) / 256, 256>>>(ei);
    k_prep<<<(MBLK * 4096 + 255) / 256, 256>>>(x);
    k_packB<<<(5 * 4096 + 255) / 256, 256>>>(W, W_res);
    dim3 ggrid(5, MBLK);
    k_gemm<<<ggrid, 256, GSMEM>>>(att_src, att_dst);
    {
        long long ng = (EN_TOT + ECHUNK - 1) / ECHUNK;
        k_sum<<<(int)((ng + 255) / 256), 256>>>();
        k_invden<<<(N_NODES * HEADS + 255) / 256, 256>>>();
        long long ngs = (EN_TOT + SCHUNK - 1) / SCHUNK;
        k_scatter<<<(int)((ngs * 16 + 255) / 256), 256>>>();
    }
    k_final<<<(N_NODES * 16 + 255) / 256, 256>>>(bias, out);
}

// round 13
// speedup vs baseline: 1.4718x; 1.0120x over previous
#include <cuda_runtime.h>
#include <cuda_bf16.h>
#include <cuda_fp16.h>
#include <cstdint>

#define N_NODES 50000
#define E_EDGES 800000
#define EN_TOT  (E_EDGES + N_NODES)
#define IN_CH   256
#define OUT_CH  64
#define HEADS   4
#define HC      256
#define NEG_SLOPE 0.2f
#define MBLK    391            // ceil(50000/128)
#define SBLK    196            // ceil(50000/256)
#define ECHUNK  8              // edges per group in k_sum
#define SCHUNK  32             // edges per group in k_scatter

// ---------------- device scratch ---------------------------------------------
__device__ uint4    g_Af[MBLK * 8192];      // A frags [mb][kc8][hl2][ks2][mt8][lane32]
__device__ uint4    g_Bf[5 * 4096];         // B frags [nb5][kc8][ks2][nt8][lane32]
__device__ __half2  g_outh[(size_t)N_NODES * 128];   // xw fp16 [N][128 half2]
__device__ float    g_res[(size_t)N_NODES * OUT_CH]; // residual fp32
__device__ float    g_alog[N_NODES * 8];
__device__ float    g_den[N_NODES * HEADS];
__device__ float4   g_ew[EN_TOT];
__device__ float    g_acc[(size_t)N_NODES * OUT_CH];
__device__ int      g_cnt[N_NODES];
__device__ int      g_bsum[SBLK];
__device__ int2     g_edges[EN_TOT];        // DST-sorted (s,d)
__device__ int      g_is64;

// ---------------- helpers ----------------------------------------------------
__device__ __forceinline__ int edge_at(const void* ei, int is64, long long idx) {
    return is64 ? (int)((const long long*)ei)[idx] : ((const int*)ei)[idx];
}
__device__ __forceinline__ float lrelu(float a) {
    return (a > 0.f) ? a : NEG_SLOPE * a;
}
__device__ __forceinline__ void cvt_hl(float x, float y, uint32_t& h, uint32_t& l) {
    __nv_bfloat162 hb = __floats2bfloat162_rn(x, y);
    float2 hf = __bfloat1622float2(hb);
    __nv_bfloat162 lb = __floats2bfloat162_rn(x - hf.x, y - hf.y);
    h = *(uint32_t*)&hb;
    l = *(uint32_t*)&lb;
}
#define MMA_BF16(d, a, b0, b1)                                                \
    asm volatile(                                                             \
        "mma.sync.aligned.m16n8k16.row.col.f32.bf16.bf16.f32 "                \
        "{%0,%1,%2,%3}, {%4,%5,%6,%7}, {%8,%9}, {%0,%1,%2,%3};"               \
        : "+f"(d[0]), "+f"(d[1]), "+f"(d[2]), "+f"(d[3])                      \
        : "r"(a.x), "r"(a.y), "r"(a.z), "r"(a.w), "r"(b0), "r"(b1))
#define REDV4(p, v)                                                           \
    asm volatile("red.global.add.v4.f32 [%0], {%1,%2,%3,%4};"                 \
                 :: "l"(p), "f"((v).x), "f"((v).y), "f"((v).z), "f"((v).w)    \
                 : "memory")
#define CP16(saddr, gptr)                                                     \
    asm volatile("cp.async.cg.shared.global [%0], [%1], 16;"                  \
                 :: "r"(saddr), "l"(gptr) : "memory")
#define CP_COMMIT() asm volatile("cp.async.commit_group;" ::: "memory")
#define CP_WAIT1()  asm volatile("cp.async.wait_group 1;" ::: "memory")
#define CP_WAIT0()  asm volatile("cp.async.wait_group 0;" ::: "memory")

// ---------------- k_detect ----------------------------------------------------
__global__ void k_detect(const unsigned* __restrict__ ei_words) {
    __shared__ unsigned s_or;
    if (threadIdx.x == 0) s_or = 0;
    __syncthreads();
    unsigned v = 0;
    for (int i = threadIdx.x; i < 4096; i += blockDim.x)
        v |= ei_words[2 * i + 1];
    if (v) atomicOr(&s_or, 1u);
    __syncthreads();
    if (threadIdx.x == 0) g_is64 = (s_or == 0) ? 1 : 0;
}

// ---------------- k_init -------------------------------------------------------
__global__ void k_init() {
    long long idx = blockIdx.x * (long long)blockDim.x + threadIdx.x;
    long long stride = (long long)gridDim.x * blockDim.x;
    long long nacc4 = (long long)N_NODES * OUT_CH / 4;
    float4 z = make_float4(0.f, 0.f, 0.f, 0.f);
    for (long long i = idx; i < nacc4; i += stride) ((float4*)g_acc)[i] = z;
    for (long long i = idx; i < (long long)N_NODES * HEADS; i += stride)
        g_den[i] = 0.f;
    for (long long i = idx; i < N_NODES; i += stride) g_cnt[i] = 0;
}

// ---------------- counting sort by DST -----------------------------------------
__global__ void k_hist(const void* __restrict__ ei) {
    int is64 = g_is64;
    int e = blockIdx.x * blockDim.x + threadIdx.x;
    if (e >= EN_TOT) return;
    int d = (e < E_EDGES) ? edge_at(ei, is64, E_EDGES + e) : e - E_EDGES;
    atomicAdd(&g_cnt[d], 1);
}

__global__ void k_scanA() {
    __shared__ int sh[256];
    int t = threadIdx.x;
    int idx = blockIdx.x * 256 + t;
    int v = (idx < N_NODES) ? g_cnt[idx] : 0;
    sh[t] = v;
    __syncthreads();
#pragma unroll
    for (int off = 1; off < 256; off <<= 1) {
        int u = (t >= off) ? sh[t - off] : 0;
        __syncthreads();
        sh[t] += u;
        __syncthreads();
    }
    if (idx < N_NODES) g_cnt[idx] = sh[t] - v;
    if (t == 255) g_bsum[blockIdx.x] = sh[255];
}

__global__ void k_scanB() {
    __shared__ int sh[256];
    int t = threadIdx.x;
    int v = (t < SBLK) ? g_bsum[t] : 0;
    sh[t] = v;
    __syncthreads();
#pragma unroll
    for (int off = 1; off < 256; off <<= 1) {
        int u = (t >= off) ? sh[t - off] : 0;
        __syncthreads();
        sh[t] += u;
        __syncthreads();
    }
    if (t < SBLK) g_bsum[t] = sh[t] - v;
}

__global__ void k_scanC() {
    int idx = blockIdx.x * blockDim.x + threadIdx.x;
    if (idx < N_NODES) g_cnt[idx] += g_bsum[idx >> 8];
}

__global__ void k_place(const void* __restrict__ ei) {
    int is64 = g_is64;
    int e = blockIdx.x * blockDim.x + threadIdx.x;
    if (e >= EN_TOT) return;
    int s, d;
    if (e < E_EDGES) {
        s = edge_at(ei, is64, e);
        d = edge_at(ei, is64, E_EDGES + e);
    } else {
        s = d = e - E_EDGES;
    }
    int pos = atomicAdd(&g_cnt[d], 1);
    g_edges[pos] = make_int2(s, d);
}

// ---------------- k_prep: X -> bf16 hi/lo fragments ----------------------------
__global__ void k_prep(const float* __restrict__ X) {
    int t = blockIdx.x * blockDim.x + threadIdx.x;
    if (t >= MBLK * 4096) return;
    int lane = t & 31;
    int mt = (t >> 5) & 7;
    int ks = (t >> 8) & 1;
    int kc = (t >> 9) & 7;
    int mb = t >> 12;

    int r0 = mb * 128 + mt * 16 + (lane >> 2);
    int tt = lane & 3;
    int k0 = kc * 32 + (ks * 8 + tt) * 2;

    float2 v[4];
    v[0] = (r0 < N_NODES) ? *(const float2*)(X + (size_t)r0 * IN_CH + k0)
                          : make_float2(0.f, 0.f);
    v[1] = (r0 + 8 < N_NODES) ? *(const float2*)(X + (size_t)(r0 + 8) * IN_CH + k0)
                              : make_float2(0.f, 0.f);
    v[2] = (r0 < N_NODES) ? *(const float2*)(X + (size_t)r0 * IN_CH + k0 + 8)
                          : make_float2(0.f, 0.f);
    v[3] = (r0 + 8 < N_NODES) ? *(const float2*)(X + (size_t)(r0 + 8) * IN_CH + k0 + 8)
                              : make_float2(0.f, 0.f);
    uint4 hv, lv;
    cvt_hl(v[0].x, v[0].y, hv.x, lv.x);
    cvt_hl(v[1].x, v[1].y, hv.y, lv.y);
    cvt_hl(v[2].x, v[2].y, hv.z, lv.z);
    cvt_hl(v[3].x, v[3].y, hv.w, lv.w);

    int base = mb * 8192 + kc * 1024 + ks * 256 + mt * 32 + lane;
    g_Af[base] = hv;
    g_Af[base + 512] = lv;
}

// ---------------- k_packB ------------------------------------------------------
__global__ void k_packB(const float* __restrict__ W, const float* __restrict__ Wr) {
    int t = blockIdx.x * blockDim.x + threadIdx.x;
    if (t >= 5 * 4096) return;
    int lane = t & 31;
    int nt = (t >> 5) & 7;
    int ks = (t >> 8) & 1;
    int kc = (t >> 9) & 7;
    int nb = t >> 12;

    int col = nb * 64 + nt * 8 + (lane >> 2);
    int tt = lane & 3;
    int k0 = kc * 32 + ks * 16 + tt * 2;

    float b00, b01, b10, b11;
    if (col < HC) {
        b00 = W[(k0) * HC + col];     b01 = W[(k0 + 1) * HC + col];
        b10 = W[(k0 + 8) * HC + col]; b11 = W[(k0 + 9) * HC + col];
    } else {
        int c = col - HC;
        b00 = Wr[(k0) * OUT_CH + c];     b01 = Wr[(k0 + 1) * OUT_CH + c];
        b10 = Wr[(k0 + 8) * OUT_CH + c]; b11 = Wr[(k0 + 9) * OUT_CH + c];
    }
    uint4 o;
    cvt_hl(b00, b01, o.x, o.z);
    cvt_hl(b10, b11, o.y, o.w);
    g_Bf[nb * 4096 + kc * 512 + ks * 256 + nt * 32 + lane] = o;
}

// ---------------- k_gemm: cp.async 2-stage pipeline + fused logits ------------
__global__ __launch_bounds__(256) void k_gemm(const float* __restrict__ att_src,
                                              const float* __restrict__ att_dst) {
    extern __shared__ uint4 sbuf[];
    __shared__ float sAttS[64], sAttD[64], sA[128], sD[128];
    int tid = threadIdx.x;
    int lane = tid & 31;
    int wid = tid >> 5;
    int mrow = wid >> 1;
    int ncol = wid & 1;
    int mb = blockIdx.y;
    int nb = blockIdx.x;

    if (nb < 4) {
        if (tid < 64) {
            sAttS[tid] = att_src[nb * 64 + tid];
            sAttD[tid] = att_dst[nb * 64 + tid];
        }
        if (tid >= 64 && tid < 192) {
            sA[tid - 64] = 0.f;
            sD[tid - 64] = 0.f;
        }
    }

    const uint4* Ab = g_Af + mb * 8192;
    const uint4* Bb = g_Bf + nb * 4096;
    uint32_t sb32 = (uint32_t)__cvta_generic_to_shared(sbuf);

    auto issue = [&](int kc, int stage) {
        uint32_t sa = sb32 + (stage * 1536) * 16;
        const uint4* gA = Ab + kc * 1024;
#pragma unroll
        for (int i = 0; i < 4; i++)
            CP16(sa + (tid + 256 * i) * 16, gA + tid + 256 * i);
        uint32_t sbB = sb32 + (stage * 1536 + 1024) * 16;
        const uint4* gB = Bb + kc * 512;
#pragma unroll
        for (int i = 0; i < 2; i++)
            CP16(sbB + (tid + 256 * i) * 16, gB + tid + 256 * i);
        CP_COMMIT();
    };

    float acc[2][4][4];
#pragma unroll
    for (int i = 0; i < 2; i++)
#pragma unroll
        for (int j = 0; j < 4; j++)
#pragma unroll
            for (int q = 0; q < 4; q++) acc[i][j][q] = 0.f;

    issue(0, 0);

#pragma unroll 1
    for (int kc = 0; kc < 8; kc++) {
        if (kc < 7) {
            issue(kc + 1, (kc + 1) & 1);
            CP_WAIT1();
        } else {
            CP_WAIT0();
        }
        __syncthreads();
        const uint4* bufA = sbuf + (kc & 1) * 1536;
        const uint4* bufB = bufA + 1024;
        uint4 ah[2][2], al[2][2];
#pragma unroll
        for (int ks = 0; ks < 2; ks++)
#pragma unroll
            for (int mt = 0; mt < 2; mt++) {
                int m = mrow * 2 + mt;
                ah[ks][mt] = bufA[ks * 256 + m * 32 + lane];
                al[ks][mt] = bufA[512 + ks * 256 + m * 32 + lane];
            }
#pragma unroll
        for (int ks = 0; ks < 2; ks++)
#pragma unroll
            for (int j = 0; j < 4; j++) {
                uint4 bv = bufB[ks * 256 + (ncol * 4 + j) * 32 + lane];
#pragma unroll
                for (int mt = 0; mt < 2; mt++) {
                    MMA_BF16(acc[mt][j], ah[ks][mt], bv.x, bv.y);
                    MMA_BF16(acc[mt][j], ah[ks][mt], bv.z, bv.w);
                    MMA_BF16(acc[mt][j], al[ks][mt], bv.x, bv.y);
                }
            }
        __syncthreads();
    }

    // epilogue: xw -> fp16 g_outh (nb<4); residual -> fp32 g_res (nb==4)
#pragma unroll
    for (int mt = 0; mt < 2; mt++)
#pragma unroll
        for (int nt = 0; nt < 4; nt++) {
            int row0 = mb * 128 + (mrow * 2 + mt) * 16 + (lane >> 2);
            int colg = (ncol * 4 + nt) * 8 + (lane & 3) * 2;   // 0..63
            if (nb < 4) {
                int hidx = (nb * 64 + colg) >> 1;
                if (row0 < N_NODES)
                    g_outh[(size_t)row0 * 128 + hidx] =
                        __floats2half2_rn(acc[mt][nt][0], acc[mt][nt][1]);
                if (row0 + 8 < N_NODES)
                    g_outh[(size_t)(row0 + 8) * 128 + hidx] =
                        __floats2half2_rn(acc[mt][nt][2], acc[mt][nt][3]);
            } else {
                float* p = g_res + (size_t)row0 * OUT_CH + colg;
                if (row0 < N_NODES)
                    *(float2*)p = make_float2(acc[mt][nt][0], acc[mt][nt][1]);
                if (row0 + 8 < N_NODES)
                    *(float2*)(p + 8 * OUT_CH) =
                        make_float2(acc[mt][nt][2], acc[mt][nt][3]);
            }
        }

    if (nb < 4) {
#pragma unroll
        for (int mt = 0; mt < 2; mt++) {
            float s0 = 0.f, d0 = 0.f, s1 = 0.f, d1 = 0.f;
#pragma unroll
            for (int nt = 0; nt < 4; nt++) {
                int cl = (ncol * 4 + nt) * 8 + (lane & 3) * 2;
                float a0 = sAttS[cl], a1 = sAttS[cl + 1];
                float b0 = sAttD[cl], b1 = sAttD[cl + 1];
                s0 += acc[mt][nt][0] * a0 + acc[mt][nt][1] * a1;
                s1 += acc[mt][nt][2] * a0 + acc[mt][nt][3] * a1;
                d0 += acc[mt][nt][0] * b0 + acc[mt][nt][1] * b1;
                d1 += acc[mt][nt][2] * b0 + acc[mt][nt][3] * b1;
            }
#pragma unroll
            for (int o = 1; o < 4; o <<= 1) {
                s0 += __shfl_xor_sync(0xffffffffu, s0, o);
                s1 += __shfl_xor_sync(0xffffffffu, s1, o);
                d0 += __shfl_xor_sync(0xffffffffu, d0, o);
                d1 += __shfl_xor_sync(0xffffffffu, d1, o);
            }
            if ((lane & 3) == 0) {
                int r = (mrow * 2 + mt) * 16 + (lane >> 2);
                atomicAdd(&sA[r], s0);
                atomicAdd(&sD[r], d0);
                atomicAdd(&sA[r + 8], s1);
                atomicAdd(&sD[r + 8], d1);
            }
        }
        __syncthreads();
        for (int r = tid; r < 128; r += 256) {
            int n = mb * 128 + r;
            if (n < N_NODES) {
                g_alog[n * 8 + nb] = sA[r];
                g_alog[n * 8 + 4 + nb] = sD[r];
            }
        }
    }
}

// ---------------- k_sum: 1 thread = ECHUNK dst-sorted edges --------------------
__global__ void k_sum() {
    long long g = blockIdx.x * (long long)blockDim.x + threadIdx.x;
    long long e0 = g * ECHUNK;
    if (e0 >= EN_TOT) return;
    float4 acc = make_float4(0.f, 0.f, 0.f, 0.f);
    int dprev = -1;
#pragma unroll
    for (int i = 0; i < ECHUNK; i++) {
        long long e = e0 + i;
        if (e >= EN_TOT) break;
        int2 ed = g_edges[e];
        float4 as = *(const float4*)(g_alog + ed.x * 8);
        float4 ad = *(const float4*)(g_alog + ed.y * 8 + 4);
        float4 ex;
        ex.x = __expf(lrelu(as.x + ad.x));
        ex.y = __expf(lrelu(as.y + ad.y));
        ex.z = __expf(lrelu(as.z + ad.z));
        ex.w = __expf(lrelu(as.w + ad.w));
        g_ew[e] = ex;
        if (ed.y != dprev) {
            if (dprev >= 0) REDV4(g_den + dprev * 4, acc);
            acc = ex;
            dprev = ed.y;
        } else {
            acc.x += ex.x; acc.y += ex.y; acc.z += ex.z; acc.w += ex.w;
        }
    }
    if (dprev >= 0) REDV4(g_den + dprev * 4, acc);
}

// ---------------- k_invden -----------------------------------------------------
__global__ void k_invden() {
    int i = blockIdx.x * blockDim.x + threadIdx.x;
    if (i < N_NODES * HEADS) g_den[i] = 1.0f / g_den[i];
}

// ---------------- k_scatter: fp16 gather, 16 lanes x SCHUNK edges --------------
__global__ void k_scatter() {
    int lane = threadIdx.x & 31;
    int sub = lane & 15;
    long long grp = ((long long)blockIdx.x * blockDim.x + threadIdx.x) >> 4;
    long long e0 = grp * SCHUNK;
    if (e0 >= EN_TOT) return;
    int c0 = sub * 4;

    float4 acc = make_float4(0.f, 0.f, 0.f, 0.f);
    int dprev = -1;
#pragma unroll 8
    for (int i = 0; i < SCHUNK; i++) {
        long long e = e0 + i;
        if (e >= EN_TOT) break;
        int2 ed = g_edges[e];
        float4 w = g_ew[e];
        float4 dn = *(const float4*)(g_den + ed.y * 4);
        float wh[4] = {w.x * dn.x, w.y * dn.y, w.z * dn.z, w.w * dn.w};

        if (ed.y != dprev) {
            if (dprev >= 0)
                REDV4(g_acc + (size_t)dprev * OUT_CH + c0, acc);
            acc = make_float4(0.f, 0.f, 0.f, 0.f);
            dprev = ed.y;
        }
#pragma unroll
        for (int h = 0; h < 4; h++) {
            uint2 raw = *(const uint2*)(g_outh + (size_t)ed.x * 128 + h * 32 + sub * 2);
            float2 a = __half22float2(*(__half2*)&raw.x);
            float2 b = __half22float2(*(__half2*)&raw.y);
            acc.x = fmaf(wh[h], a.x, acc.x);
            acc.y = fmaf(wh[h], a.y, acc.y);
            acc.z = fmaf(wh[h], b.x, acc.z);
            acc.w = fmaf(wh[h], b.y, acc.w);
        }
    }
    if (dprev >= 0)
        REDV4(g_acc + (size_t)dprev * OUT_CH + c0, acc);
}

// ---------------- k_final ------------------------------------------------------
__global__ void k_final(const float* __restrict__ bias, float* __restrict__ out) {
    int i = blockIdx.x * blockDim.x + threadIdx.x;
    if (i >= N_NODES * 16) return;
    int n = i >> 4;
    int c = (i & 15) * 4;
    float4 a = *(const float4*)(g_acc + (size_t)n * OUT_CH + c);
    float4 b = *(const float4*)(bias + c);
    float4 r = *(const float4*)(g_res + (size_t)n * OUT_CH + c);
    float4 o;
    o.x = fmaxf(0.f, 0.25f * a.x + b.x + r.x);
    o.y = fmaxf(0.f, 0.25f * a.y + b.y + r.y);
    o.z = fmaxf(0.f, 0.25f * a.z + b.z + r.z);
    o.w = fmaxf(0.f, 0.25f * a.w + b.w + r.w);
    *(float4*)(out + (size_t)n * OUT_CH + c) = o;
}

// ---------------- launch -------------------------------------------------------
extern "C" void kernel_launch(void* const* d_in, const int* in_sizes, int n_in,
                              void* d_out, int out_size) {
    const float* x       = (const float*)d_in[0];
    const void*  ei      = d_in[1];
    const float* W       = (const float*)d_in[2];
    const float* att_src = (const float*)d_in[3];
    const float* att_dst = (const float*)d_in[4];
    const float* bias    = (const float*)d_in[5];
    const float* W_res   = (const float*)d_in[6];
    float* out = (float*)d_out;

    static cudaStream_t s1;
    static cudaEvent_t evFork, evJoin;
    static int inited = 0;
    if (!inited) {
        cudaStreamCreateWithFlags(&s1, cudaStreamNonBlocking);
        cudaEventCreateWithFlags(&evFork, cudaEventDisableTiming);
        cudaEventCreateWithFlags(&evJoin, cudaEventDisableTiming);
        cudaFuncSetAttribute(k_gemm, cudaFuncAttributeMaxDynamicSharedMemorySize,
                             2 * 1536 * 16);
        inited = 1;
    }
    const int GSMEM = 2 * 1536 * 16;   // 49152 B

    k_detect<<<1, 256>>>((const unsigned*)ei);
    k_init<<<1024, 256>>>();

    // fork: sort chain on s1, GEMM chain on main stream
    cudaEventRecord(evFork, 0);
    cudaStreamWaitEvent(s1, evFork, 0);
    k_hist<<<(EN_TOT + 255) / 256, 256, 0, s1>>>(ei);
    k_scanA<<<SBLK, 256, 0, s1>>>();
    k_scanB<<<1, 256, 0, s1>>>();
    k_scanC<<<SBLK, 256, 0, s1>>>();
    k_place<<<(EN_TOT + 255) / 256, 256, 0, s1>>>(ei);
    cudaEventRecord(evJoin, s1);

    k_prep<<<(MBLK * 4096 + 255) / 256, 256>>>(x);
    k_packB<<<(5 * 4096 + 255) / 256, 256>>>(W, W_res);
    dim3 ggrid(5, MBLK);
    k_gemm<<<ggrid, 256, GSMEM>>>(att_src, att_dst);

    // join before edge phase
    cudaStreamWaitEvent(0, evJoin, 0);
    {
        long long ng = (EN_TOT + ECHUNK - 1) / ECHUNK;
        k_sum<<<(int)((ng + 255) / 256), 256>>>();
        k_invden<<<(N_NODES * HEADS + 255) / 256, 256>>>();
        long long ngs = (EN_TOT + SCHUNK - 1) / SCHUNK;
        k_scatter<<<(int)((ngs * 16 + 255) / 256), 256>>>();
    }
    k_final<<<(N_NODES * 16 + 255) / 256, 256>>>(bias, out);
}